// round 6
// baseline (speedup 1.0000x reference)
#include <cuda_runtime.h>
#include <cstdint>
#include <math.h>

#define T_  1024
#define H_  1024
#define I_  1024
#define E_  16
#define K_  8
#define TK_ (T_ * K_)

// ---------------- scratch (no allocs allowed) ----------------
__device__ int    g_off[E_ + 1];
__device__ int    g_ptok[TK_];
__device__ int    g_pos[TK_];
__device__ float  g_gu[(size_t)TK_ * 2 * I_];    // raw gate/up, fp32, 64 MB
__device__ float  g_down[(size_t)TK_ * H_];      // 32 MB
__device__ int8_t q_xh[(size_t)T_ * H_],  q_xl[(size_t)T_ * H_];
__device__ float  q_xs[T_];
__device__ int8_t q_wgh[(size_t)E_ * 2 * I_ * H_], q_wgl[(size_t)E_ * 2 * I_ * H_];
__device__ float  q_wgs[E_ * 2 * I_];
__device__ int8_t q_wdh[(size_t)E_ * H_ * I_], q_wdl[(size_t)E_ * H_ * I_];
__device__ float  q_wds[E_ * H_];
__device__ int8_t q_ah[(size_t)TK_ * I_], q_al[(size_t)TK_ * I_];
__device__ float  q_as[TK_];

// ---------------- helpers ----------------
__device__ __forceinline__ uint32_t smem_u32(const void* p) {
    uint32_t a;
    asm("{ .reg .u64 t; cvta.to.shared.u64 t, %1; cvt.u32.u64 %0, t; }" : "=r"(a) : "l"(p));
    return a;
}
__device__ __forceinline__ float silu_f(float x) { return x / (1.0f + expf(-x)); }

__device__ __forceinline__ void mma_s8(int* c, const uint32_t* a, const uint32_t* b) {
    asm volatile(
        "mma.sync.aligned.m16n8k32.row.col.s32.s8.s8.s32 "
        "{%0,%1,%2,%3}, {%4,%5,%6,%7}, {%8,%9}, {%0,%1,%2,%3};"
        : "+r"(c[0]), "+r"(c[1]), "+r"(c[2]), "+r"(c[3])
        : "r"(a[0]), "r"(a[1]), "r"(a[2]), "r"(a[3]), "r"(b[0]), "r"(b[1]));
}
__device__ __forceinline__ void ldsm4(uint32_t* d, uint32_t addr) {
    asm volatile("ldmatrix.sync.aligned.m8n8.x4.shared.b16 {%0,%1,%2,%3}, [%4];"
        : "=r"(d[0]), "=r"(d[1]), "=r"(d[2]), "=r"(d[3]) : "r"(addr));
}
__device__ __forceinline__ void cp16(uint32_t dst, const void* src) {
    asm volatile("cp.async.cg.shared.global [%0], [%1], 16;" :: "r"(dst), "l"(src));
}

// ---------------- routing: stable chunked histogram ----------------
__global__ void route_kernel(const int* __restrict__ idx) {
    __shared__ int cnt[1024];
    __shared__ int off[1025];
    __shared__ int s_stride;
    int tid = threadIdx.x;
    if (tid == 0) {
        int nz = 0;
        #pragma unroll 1
        for (int j = 1; j < 256; j += 2) nz |= (idx[j] != 0);
        s_stride = nz ? 1 : 2;   // int32 vs int64 payload
    }
    __syncthreads();
    int stride = s_stride;
    int e = tid >> 6, c = tid & 63;
    int j0 = c * 128, j1 = j0 + 128;
    int cn = 0;
    for (int j = j0; j < j1; j++) cn += (idx[j * stride] == e);
    cnt[tid] = cn;
    __syncthreads();
    if (tid == 0) {
        int a = 0;
        for (int i = 0; i < 1024; i++) { off[i] = a; a += cnt[i]; }
        off[1024] = a;
        for (int ee = 0; ee <= E_; ee++) g_off[ee] = off[ee * 64];
    }
    __syncthreads();
    int p = off[tid];
    for (int j = j0; j < j1; j++) {
        if (idx[j * stride] == e) { g_ptok[p] = j >> 3; g_pos[j] = p; p++; }
    }
}

// ---------------- row quantization: a = sc*(h + l/254), sc = rowmax/127 ----------------
__device__ __forceinline__ void quant_store(float4 v, float s, int8_t* qh, int8_t* ql,
                                            int tid) {
    float inv = 127.0f / s;
    float scq = s * (1.0f / 127.0f);
    int hx = __float2int_rn(v.x * inv);
    int hy = __float2int_rn(v.y * inv);
    int hz = __float2int_rn(v.z * inv);
    int hw = __float2int_rn(v.w * inv);
    float f254 = 254.0f * inv;
    int lx = __float2int_rn((v.x - hx * scq) * f254);
    int ly = __float2int_rn((v.y - hy * scq) * f254);
    int lz = __float2int_rn((v.z - hz * scq) * f254);
    int lw = __float2int_rn((v.w - hw * scq) * f254);
    ((char4*)qh)[tid] = make_char4((char)hx, (char)hy, (char)hz, (char)hw);
    ((char4*)ql)[tid] = make_char4((char)lx, (char)ly, (char)lz, (char)lw);
}

__device__ __forceinline__ float block_rowmax(float m, int tid) {
    #pragma unroll
    for (int o = 16; o; o >>= 1) m = fmaxf(m, __shfl_xor_sync(0xFFFFFFFFu, m, o));
    __shared__ float red[8];
    __shared__ float s_s;
    if ((tid & 31) == 0) red[tid >> 5] = m;
    __syncthreads();
    if (tid == 0) {
        float mm = red[0];
        #pragma unroll
        for (int i = 1; i < 8; i++) mm = fmaxf(mm, red[i]);
        s_s = fmaxf(mm, 1e-20f);
    }
    __syncthreads();
    return s_s;
}

__global__ void quant_rows(const float* __restrict__ src, int8_t* __restrict__ qh,
                           int8_t* __restrict__ ql, float* __restrict__ sc) {
    int row = blockIdx.x, tid = threadIdx.x;
    float4 v = ((const float4*)(src + (size_t)row * 1024))[tid];
    float m = fmaxf(fmaxf(fabsf(v.x), fabsf(v.y)), fmaxf(fabsf(v.z), fabsf(v.w)));
    float s = block_rowmax(m, tid);
    quant_store(v, s, qh + (size_t)row * 1024, ql + (size_t)row * 1024, tid);
    if (tid == 0) sc[row] = s * (1.0f / 127.0f);
}

// silu(gate)*up from raw g_gu row, then quantize
__global__ void qact_kernel() {
    int p = blockIdx.x, tid = threadIdx.x;
    const float* row = g_gu + (size_t)p * 2048;
    float4 g = ((const float4*)row)[tid];
    float4 u = ((const float4*)(row + 1024))[tid];
    float4 a;
    a.x = silu_f(g.x) * u.x; a.y = silu_f(g.y) * u.y;
    a.z = silu_f(g.z) * u.z; a.w = silu_f(g.w) * u.w;
    float m = fmaxf(fmaxf(fabsf(a.x), fabsf(a.y)), fmaxf(fabsf(a.z), fabsf(a.w)));
    float s = block_rowmax(m, tid);
    quant_store(a, s, q_ah + (size_t)p * 1024, q_al + (size_t)p * 1024, tid);
    if (tid == 0) q_as[p] = s * (1.0f / 127.0f);
}

// ---------------------------------------------------------------------------
// int8 grouped GEMM: D[p][n] = sa[p]*sb[n]*(HH + (HL+LH)/254)
// CTA 128(M pairs) x 128(N), BK=64, 256 thr, 8 warps (2x4), warp 64x32.
// 3-stage cp.async pipeline; ldmatrix fragments; 80B-padded rows (conflict-free).
// ---------------------------------------------------------------------------
#define STG_BYTES 40960          // 4 planes x 128 rows x 80B
#define GSMEM (3 * STG_BYTES)    // 122880

template <int GATHER>
__global__ void __launch_bounds__(256, 1)
gemm_i8(const int8_t* __restrict__ Agh, const int8_t* __restrict__ Agl,
        const float* __restrict__ Asc,
        const int8_t* __restrict__ Bgh, const int8_t* __restrict__ Bgl,
        const float* __restrict__ Bsc,
        float* __restrict__ D, int ncols) {
    int e    = blockIdx.z;
    int rbeg = g_off[e], rend = g_off[e + 1];
    int row0 = rbeg + blockIdx.y * 128;
    if (row0 >= rend) return;
    int n0 = blockIdx.x * 128;

    extern __shared__ char smem[];
    uint32_t sb = smem_u32(smem);

    int tid = threadIdx.x, wid = tid >> 5, lane = tid & 31;
    int gid = lane >> 2, tig = lane & 3;
    int wm = (wid >> 2) * 64, wn = (wid & 3) * 32;

    // global->smem loader mapping: each thread owns 2 rows (lr, lr+64), 16B col lc
    int lr = tid >> 2, lc = (tid & 3) * 16;
    int pa0 = row0 + lr;      if (pa0 >= rend) pa0 = rend - 1;
    int pa1 = row0 + lr + 64; if (pa1 >= rend) pa1 = rend - 1;
    size_t ra0 = GATHER ? (size_t)g_ptok[pa0] * 1024 : (size_t)pa0 * 1024;
    size_t ra1 = GATHER ? (size_t)g_ptok[pa1] * 1024 : (size_t)pa1 * 1024;
    const int8_t* a0h = Agh + ra0 + lc;  const int8_t* a0l = Agl + ra0 + lc;
    const int8_t* a1h = Agh + ra1 + lc;  const int8_t* a1l = Agl + ra1 + lc;
    size_t rb0 = ((size_t)e * ncols + n0 + lr) * 1024;
    size_t rb1 = rb0 + (size_t)64 * 1024;
    const int8_t* b0h = Bgh + rb0 + lc;  const int8_t* b0l = Bgl + rb0 + lc;
    const int8_t* b1h = Bgh + rb1 + lc;  const int8_t* b1l = Bgl + rb1 + lc;
    uint32_t sd0 = (uint32_t)(lr * 80 + lc);
    uint32_t sd1 = (uint32_t)((lr + 64) * 80 + lc);

    auto issue = [&](int stg, int k0) {
        uint32_t b = sb + stg * STG_BYTES;
        cp16(b + sd0,          a0h + k0);
        cp16(b + sd1,          a1h + k0);
        cp16(b + 10240 + sd0,  a0l + k0);
        cp16(b + 10240 + sd1,  a1l + k0);
        cp16(b + 20480 + sd0,  b0h + k0);
        cp16(b + 20480 + sd1,  b1h + k0);
        cp16(b + 30720 + sd0,  b0l + k0);
        cp16(b + 30720 + sd1,  b1l + k0);
        asm volatile("cp.async.commit_group;" ::: "memory");
    };

    issue(0, 0);
    issue(1, 64);

    int accH[4][4][4], accC[4][4][4];
    #pragma unroll
    for (int a = 0; a < 4; a++)
        #pragma unroll
        for (int b = 0; b < 4; b++)
            #pragma unroll
            for (int q = 0; q < 4; q++) { accH[a][b][q] = 0; accC[a][b][q] = 0; }

    // ldmatrix lane-address parts (quad = lane>>3)
    uint32_t aoff = (uint32_t)((((lane >> 3) & 1) * 8 + (lane & 7)) * 80 + (lane >> 4) * 16);
    uint32_t boff = (uint32_t)(((lane >> 4) * 8 + (lane & 7)) * 80 + ((lane >> 3) & 1) * 16);

    for (int it = 0; it < 16; it++) {
        if (it < 15) asm volatile("cp.async.wait_group 1;" ::: "memory");
        else         asm volatile("cp.async.wait_group 0;" ::: "memory");
        __syncthreads();
        uint32_t bb = sb + (it % 3) * STG_BYTES;
        #pragma unroll
        for (int s = 0; s < 2; s++) {
            uint32_t kb = s * 32;
            uint32_t ah[4][4], al[4][4];
            #pragma unroll
            for (int mt = 0; mt < 4; mt++) {
                uint32_t ad = bb + (wm + mt * 16) * 80 + kb + aoff;
                ldsm4(ah[mt], ad);
                ldsm4(al[mt], ad + 10240);
            }
            uint32_t bh[4][2], bl[4][2];
            #pragma unroll
            for (int np = 0; np < 2; np++) {
                uint32_t r4[4], s4[4];
                uint32_t bd = bb + 20480 + (wn + np * 16) * 80 + kb + boff;
                ldsm4(r4, bd);
                ldsm4(s4, bd + 10240);
                bh[2*np][0] = r4[0]; bh[2*np][1] = r4[1];
                bh[2*np+1][0] = r4[2]; bh[2*np+1][1] = r4[3];
                bl[2*np][0] = s4[0]; bl[2*np][1] = s4[1];
                bl[2*np+1][0] = s4[2]; bl[2*np+1][1] = s4[3];
            }
            #pragma unroll
            for (int mt = 0; mt < 4; mt++)
                #pragma unroll
                for (int nt = 0; nt < 4; nt++) {
                    mma_s8(accH[mt][nt], ah[mt], bh[nt]);
                    mma_s8(accC[mt][nt], ah[mt], bl[nt]);
                    mma_s8(accC[mt][nt], al[mt], bh[nt]);
                }
        }
        if (it + 2 < 16) issue((it + 2) % 3, (it + 2) * 64);
    }

    // epilogue
    #pragma unroll
    for (int mt = 0; mt < 4; mt++) {
        int rr0 = row0 + wm + mt * 16 + gid;
        int rr1 = rr0 + 8;
        float sa0 = 0.f, sa1 = 0.f;
        if (rr0 < rend) sa0 = GATHER ? Asc[g_ptok[rr0]] : Asc[rr0];
        if (rr1 < rend) sa1 = GATHER ? Asc[g_ptok[rr1]] : Asc[rr1];
        #pragma unroll
        for (int nt = 0; nt < 4; nt++) {
            int cc = n0 + wn + nt * 8 + 2 * tig;
            float sb0 = Bsc[e * ncols + cc];
            float sb1 = Bsc[e * ncols + cc + 1];
            const float r254 = 1.0f / 254.0f;
            if (rr0 < rend) {
                float2 o;
                o.x = sa0 * sb0 * ((float)accH[mt][nt][0] + (float)accC[mt][nt][0] * r254);
                o.y = sa0 * sb1 * ((float)accH[mt][nt][1] + (float)accC[mt][nt][1] * r254);
                *(float2*)&D[(size_t)rr0 * ncols + cc] = o;
            }
            if (rr1 < rend) {
                float2 o;
                o.x = sa1 * sb0 * ((float)accH[mt][nt][2] + (float)accC[mt][nt][2] * r254);
                o.y = sa1 * sb1 * ((float)accH[mt][nt][3] + (float)accC[mt][nt][3] * r254);
                *(float2*)&D[(size_t)rr1 * ncols + cc] = o;
            }
        }
    }
}

// ---------------- combine ----------------
__global__ void combine_kernel(const float* __restrict__ tw, float* __restrict__ out) {
    int t = blockIdx.x;
    __shared__ int   pos[K_];
    __shared__ float w[K_];
    if (threadIdx.x < K_) {
        pos[threadIdx.x] = g_pos[t * K_ + threadIdx.x];
        w[threadIdx.x]   = tw[t * K_ + threadIdx.x];
    }
    __syncthreads();
    int h = 4 * threadIdx.x;
    float4 acc = {0.f, 0.f, 0.f, 0.f};
    #pragma unroll
    for (int k = 0; k < K_; k++) {
        float4 v = *(const float4*)&g_down[(size_t)pos[k] * H_ + h];
        float wk = w[k];
        acc.x += wk * v.x; acc.y += wk * v.y;
        acc.z += wk * v.z; acc.w += wk * v.w;
    }
    *(float4*)&out[(size_t)t * H_ + h] = acc;
}

// ---------------- launch ----------------
extern "C" void kernel_launch(void* const* d_in, const int* in_sizes, int n_in,
                              void* d_out, int out_size) {
    const float* hidden = (const float*)d_in[0];
    const int*   tk_idx = (const int*)d_in[1];
    const float* tk_w   = (const float*)d_in[2];
    const float* gup    = (const float*)d_in[3];
    const float* dproj  = (const float*)d_in[4];
    float*       out    = (float*)d_out;

    int8_t *xh, *xl, *wgh, *wgl, *wdh, *wdl, *ah, *al;
    float *xs, *wgs, *wds, *as, *gu_p, *down_p;
    cudaGetSymbolAddress((void**)&xh,  q_xh);  cudaGetSymbolAddress((void**)&xl,  q_xl);
    cudaGetSymbolAddress((void**)&xs,  q_xs);
    cudaGetSymbolAddress((void**)&wgh, q_wgh); cudaGetSymbolAddress((void**)&wgl, q_wgl);
    cudaGetSymbolAddress((void**)&wgs, q_wgs);
    cudaGetSymbolAddress((void**)&wdh, q_wdh); cudaGetSymbolAddress((void**)&wdl, q_wdl);
    cudaGetSymbolAddress((void**)&wds, q_wds);
    cudaGetSymbolAddress((void**)&ah,  q_ah);  cudaGetSymbolAddress((void**)&al,  q_al);
    cudaGetSymbolAddress((void**)&as,  q_as);
    cudaGetSymbolAddress((void**)&gu_p,   g_gu);
    cudaGetSymbolAddress((void**)&down_p, g_down);

    cudaFuncSetAttribute(gemm_i8<1>, cudaFuncAttributeMaxDynamicSharedMemorySize, GSMEM);
    cudaFuncSetAttribute(gemm_i8<0>, cudaFuncAttributeMaxDynamicSharedMemorySize, GSMEM);

    route_kernel<<<1, 1024>>>(tk_idx);
    quant_rows<<<T_, 256>>>(hidden, xh, xl, xs);
    quant_rows<<<E_ * 2 * I_, 256>>>(gup, wgh, wgl, wgs);
    quant_rows<<<E_ * H_, 256>>>(dproj, wdh, wdl, wds);

    gemm_i8<1><<<dim3(2 * I_ / 128, TK_ / 128, E_), 256, GSMEM>>>(
        xh, xl, xs, wgh, wgl, wgs, gu_p, 2 * I_);
    qact_kernel<<<TK_, 256>>>();
    gemm_i8<0><<<dim3(H_ / 128, TK_ / 128, E_), 256, GSMEM>>>(
        ah, al, as, wdh, wdl, wds, down_p, H_);
    combine_kernel<<<T_, 256>>>(tk_w, out);
}

// round 7
// speedup vs baseline: 1.4517x; 1.4517x over previous
#include <cuda_runtime.h>
#include <cuda_bf16.h>
#include <cstdint>
#include <math.h>

#define T_  1024
#define H_  1024
#define I_  1024
#define E_  16
#define K_  8
#define TK_ (T_ * K_)

// ---------------- scratch (no allocs allowed) ----------------
__device__ int      g_off[E_ + 1];
__device__ int      g_ptok[TK_];
__device__ int      g_pos[TK_];
__device__ uint16_t q_xh[(size_t)T_ * H_],         q_xm[(size_t)T_ * H_];
__device__ uint16_t q_gh[(size_t)E_ * 2 * I_ * H_], q_gm[(size_t)E_ * 2 * I_ * H_];
__device__ uint16_t q_dh[(size_t)E_ * H_ * I_],     q_dm[(size_t)E_ * H_ * I_];
__device__ uint16_t q_ah[(size_t)TK_ * I_],         q_am[(size_t)TK_ * I_];
__device__ float    g_down[(size_t)TK_ * H_];       // 32 MB

// ---------------- helpers ----------------
__device__ __forceinline__ uint32_t smem_u32(const void* p) {
    uint32_t a;
    asm("{ .reg .u64 t; cvta.to.shared.u64 t, %1; cvt.u32.u64 %0, t; }" : "=r"(a) : "l"(p));
    return a;
}
__device__ __forceinline__ float silu_f(float x) { return x / (1.0f + expf(-x)); }

__device__ __forceinline__ void mma_bf16(float* c, const uint32_t* a, const uint32_t* b) {
    asm volatile(
        "mma.sync.aligned.m16n8k16.row.col.f32.bf16.bf16.f32 "
        "{%0,%1,%2,%3}, {%4,%5,%6,%7}, {%8,%9}, {%0,%1,%2,%3};"
        : "+f"(c[0]), "+f"(c[1]), "+f"(c[2]), "+f"(c[3])
        : "r"(a[0]), "r"(a[1]), "r"(a[2]), "r"(a[3]), "r"(b[0]), "r"(b[1]));
}
__device__ __forceinline__ void ldsm4(uint32_t* d, uint32_t addr) {
    asm volatile("ldmatrix.sync.aligned.m8n8.x4.shared.b16 {%0,%1,%2,%3}, [%4];"
        : "=r"(d[0]), "=r"(d[1]), "=r"(d[2]), "=r"(d[3]) : "r"(addr));
}
__device__ __forceinline__ void cp16(uint32_t dst, const void* src) {
    asm volatile("cp.async.cg.shared.global [%0], [%1], 16;" :: "r"(dst), "l"(src));
}
__device__ __forceinline__ uint32_t b2u(__nv_bfloat162 v) {
    return *reinterpret_cast<uint32_t*>(&v);
}

// ---------------- routing: stable chunked histogram ----------------
__global__ void route_kernel(const int* __restrict__ idx) {
    __shared__ int cnt[1024];
    __shared__ int off[1025];
    __shared__ int s_stride;
    int tid = threadIdx.x;
    if (tid == 0) {
        int nz = 0;
        #pragma unroll 1
        for (int j = 1; j < 256; j += 2) nz |= (idx[j] != 0);
        s_stride = nz ? 1 : 2;   // int32 vs int64 payload
    }
    __syncthreads();
    int stride = s_stride;
    int e = tid >> 6, c = tid & 63;
    int j0 = c * 128, j1 = j0 + 128;
    int cn = 0;
    for (int j = j0; j < j1; j++) cn += (idx[j * stride] == e);
    cnt[tid] = cn;
    __syncthreads();
    if (tid == 0) {
        int a = 0;
        for (int i = 0; i < 1024; i++) { off[i] = a; a += cnt[i]; }
        off[1024] = a;
        for (int ee = 0; ee <= E_; ee++) g_off[ee] = off[ee * 64];
    }
    __syncthreads();
    int p = off[tid];
    for (int j = j0; j < j1; j++) {
        if (idx[j * stride] == e) { g_ptok[p] = j >> 3; g_pos[j] = p; p++; }
    }
}

// ---------------- elementwise bf16 hi/mid split (pure bandwidth) ----------------
__global__ void split_kernel(const float* __restrict__ src,
                             uint16_t* __restrict__ h, uint16_t* __restrict__ m) {
    int idx = blockIdx.x * 256 + threadIdx.x;
    float4 v = ((const float4*)src)[idx];
    __nv_bfloat162 h01 = __floats2bfloat162_rn(v.x, v.y);
    __nv_bfloat162 h23 = __floats2bfloat162_rn(v.z, v.w);
    float rx = v.x - __bfloat162float(h01.x);
    float ry = v.y - __bfloat162float(h01.y);
    float rz = v.z - __bfloat162float(h23.x);
    float rw = v.w - __bfloat162float(h23.y);
    __nv_bfloat162 m01 = __floats2bfloat162_rn(rx, ry);
    __nv_bfloat162 m23 = __floats2bfloat162_rn(rz, rw);
    ((uint2*)h)[idx] = make_uint2(b2u(h01), b2u(h23));
    ((uint2*)m)[idx] = make_uint2(b2u(m01), b2u(m23));
}

// ---------------------------------------------------------------------------
// Pure-tensor grouped GEMM on pre-split bf16 planes.
// acc = Ah*Bh + Ah*Bm + Am*Bh (3 mma into same fp32 acc).
// CTA 128(M) x 128(N), BK=64 bf16, 256 thr, 8 warps (4m x 2n), warp 32x64.
// 3-stage cp.async pipeline, ldmatrix fragments, 144B-pitch rows.
// FUSE=1 (GEMM1): A gathered via g_ptok, B rows = 64 gate + 64 up of i-block n0;
//                 epilogue silu(gate)*up -> act bf16 hi/mid planes.
// FUSE=0 (GEMM2): A = act planes (rows = pairs), B = down planes; -> g_down f32.
// ---------------------------------------------------------------------------
#define PITCH 144
#define PLB   (128 * PITCH)          // 18432 bytes per plane
#define STGB  (4 * PLB)              // 73728 bytes per stage
#define GSMEM (3 * STGB)             // 221184

template <int FUSE>
__global__ void __launch_bounds__(256, 1)
gemm_pre(const uint16_t* __restrict__ Agh, const uint16_t* __restrict__ Agm,
         const uint16_t* __restrict__ Bgh, const uint16_t* __restrict__ Bgm,
         float* __restrict__ D) {
    int e    = blockIdx.z;
    int rbeg = g_off[e], rend = g_off[e + 1];
    int row0 = rbeg + blockIdx.y * 128;
    if (row0 >= rend) return;
    int n0 = blockIdx.x * (FUSE ? 64 : 128);

    extern __shared__ char smem[];
    uint32_t sb = smem_u32(smem);

    int tid = threadIdx.x, wid = tid >> 5, lane = tid & 31;
    int gid = lane >> 2, tig = lane & 3;
    int wm = (wid >> 1) * 32, wn = (wid & 1) * 64;

    // loader mapping: per q, 16B chunk (r = row 0..127, c = chunk 0..7)
    const char* sAh[4]; const char* sAm[4];
    const char* sBh[4]; const char* sBm[4];
    uint32_t sd[4];
    #pragma unroll
    for (int q = 0; q < 4; q++) {
        int idx = tid + 256 * q;
        int r = idx >> 3, c = idx & 7;
        int p = row0 + r; if (p >= rend) p = rend - 1;
        size_t arow = FUSE ? (size_t)g_ptok[p] : (size_t)p;
        sAh[q] = (const char*)Agh + arow * 2048 + c * 16;
        sAm[q] = (const char*)Agm + arow * 2048 + c * 16;
        int br;
        if (FUSE) br = (r < 64) ? (n0 + r) : (I_ + n0 + r - 64);
        else      br = n0 + r;
        size_t brow = (size_t)e * (FUSE ? 2 * I_ : H_) + br;
        sBh[q] = (const char*)Bgh + brow * 2048 + c * 16;
        sBm[q] = (const char*)Bgm + brow * 2048 + c * 16;
        sd[q] = (uint32_t)(r * PITCH + c * 16);
    }

    auto issue = [&](int stg, int it) {
        uint32_t b = sb + stg * STGB;
        int ko = it * 128;   // 64 bf16 = 128 bytes per k-tile
        #pragma unroll
        for (int q = 0; q < 4; q++) {
            cp16(b + sd[q],           sAh[q] + ko);
            cp16(b + PLB + sd[q],     sAm[q] + ko);
            cp16(b + 2 * PLB + sd[q], sBh[q] + ko);
            cp16(b + 3 * PLB + sd[q], sBm[q] + ko);
        }
        asm volatile("cp.async.commit_group;" ::: "memory");
    };

    issue(0, 0);
    issue(1, 1);

    float acc[2][8][4];
    #pragma unroll
    for (int mt = 0; mt < 2; mt++)
        #pragma unroll
        for (int nt = 0; nt < 8; nt++)
            #pragma unroll
            for (int q = 0; q < 4; q++) acc[mt][nt][q] = 0.f;

    // ldmatrix lane offsets (verified layout, 16B k-halves)
    uint32_t aoff = (uint32_t)((((lane >> 3) & 1) * 8 + (lane & 7)) * PITCH + (lane >> 4) * 16);
    uint32_t boff = (uint32_t)(((lane >> 4) * 8 + (lane & 7)) * PITCH + ((lane >> 3) & 1) * 16);

    const int NIT = 16;   // 1024 / 64
    for (int it = 0; it < NIT; it++) {
        if (it < NIT - 1) asm volatile("cp.async.wait_group 1;" ::: "memory");
        else              asm volatile("cp.async.wait_group 0;" ::: "memory");
        __syncthreads();
        uint32_t bb = sb + (it % 3) * STGB;
        #pragma unroll
        for (int ks = 0; ks < 4; ks++) {
            uint32_t kb = ks * 32;   // 16 bf16 per k-step
            uint32_t ah[2][4], am[2][4];
            #pragma unroll
            for (int mt = 0; mt < 2; mt++) {
                uint32_t ad = bb + (wm + mt * 16) * PITCH + kb + aoff;
                ldsm4(ah[mt], ad);
                ldsm4(am[mt], ad + PLB);
            }
            uint32_t bh[8][2], bm[8][2];
            #pragma unroll
            for (int np = 0; np < 4; np++) {
                uint32_t r4[4], s4[4];
                uint32_t bd = bb + 2 * PLB + (wn + np * 16) * PITCH + kb + boff;
                ldsm4(r4, bd);
                ldsm4(s4, bd + PLB);
                bh[2*np][0] = r4[0]; bh[2*np][1] = r4[1];
                bh[2*np+1][0] = r4[2]; bh[2*np+1][1] = r4[3];
                bm[2*np][0] = s4[0]; bm[2*np][1] = s4[1];
                bm[2*np+1][0] = s4[2]; bm[2*np+1][1] = s4[3];
            }
            #pragma unroll
            for (int mt = 0; mt < 2; mt++)
                #pragma unroll
                for (int nt = 0; nt < 8; nt++) {
                    mma_bf16(acc[mt][nt], ah[mt], bh[nt]);
                    mma_bf16(acc[mt][nt], ah[mt], bm[nt]);
                    mma_bf16(acc[mt][nt], am[mt], bh[nt]);
                }
        }
        if (it + 2 < NIT) issue((it + 2) % 3, it + 2);
    }

    if (FUSE) {
        // stage fp32 tile, recombine gate(0..63)/up(64..127), split act -> bf16 planes
        __syncthreads();
        float* s = (float*)smem;   // 128 x 132 fp32 = 67.6 KB
        #pragma unroll
        for (int mt = 0; mt < 2; mt++) {
            int r = wm + mt * 16 + gid;
            #pragma unroll
            for (int nt = 0; nt < 8; nt++) {
                int c = wn + nt * 8 + 2 * tig;
                *(float2*)&s[r * 132 + c]       = make_float2(acc[mt][nt][0], acc[mt][nt][1]);
                *(float2*)&s[(r + 8) * 132 + c] = make_float2(acc[mt][nt][2], acc[mt][nt][3]);
            }
        }
        __syncthreads();
        #pragma unroll
        for (int j = 0; j < 8; j++) {
            int u = tid + 256 * j;
            int r = u >> 4, cf = u & 15;
            int c = cf * 4;
            int p = row0 + r;
            if (p < rend) {
                float4 g = *(const float4*)&s[r * 132 + c];
                float4 up = *(const float4*)&s[r * 132 + 64 + c];
                float ax = silu_f(g.x) * up.x, ay = silu_f(g.y) * up.y;
                float az = silu_f(g.z) * up.z, aw = silu_f(g.w) * up.w;
                __nv_bfloat162 h01 = __floats2bfloat162_rn(ax, ay);
                __nv_bfloat162 h23 = __floats2bfloat162_rn(az, aw);
                __nv_bfloat162 m01 = __floats2bfloat162_rn(ax - __bfloat162float(h01.x),
                                                           ay - __bfloat162float(h01.y));
                __nv_bfloat162 m23 = __floats2bfloat162_rn(az - __bfloat162float(h23.x),
                                                           aw - __bfloat162float(h23.y));
                size_t o = (size_t)p * 1024 + n0 + c;
                *(uint2*)&q_ah[o] = make_uint2(b2u(h01), b2u(h23));
                *(uint2*)&q_am[o] = make_uint2(b2u(m01), b2u(m23));
            }
        }
    } else {
        #pragma unroll
        for (int mt = 0; mt < 2; mt++) {
            int rr0 = row0 + wm + mt * 16 + gid;
            int rr1 = rr0 + 8;
            #pragma unroll
            for (int nt = 0; nt < 8; nt++) {
                int cc = n0 + wn + nt * 8 + 2 * tig;
                if (rr0 < rend)
                    *(float2*)&D[(size_t)rr0 * H_ + cc] = make_float2(acc[mt][nt][0], acc[mt][nt][1]);
                if (rr1 < rend)
                    *(float2*)&D[(size_t)rr1 * H_ + cc] = make_float2(acc[mt][nt][2], acc[mt][nt][3]);
            }
        }
    }
}

// ---------------- combine ----------------
__global__ void combine_kernel(const float* __restrict__ tw, float* __restrict__ out) {
    int t = blockIdx.x;
    __shared__ int   pos[K_];
    __shared__ float w[K_];
    if (threadIdx.x < K_) {
        pos[threadIdx.x] = g_pos[t * K_ + threadIdx.x];
        w[threadIdx.x]   = tw[t * K_ + threadIdx.x];
    }
    __syncthreads();
    int h = 4 * threadIdx.x;
    float4 acc = {0.f, 0.f, 0.f, 0.f};
    #pragma unroll
    for (int k = 0; k < K_; k++) {
        float4 v = *(const float4*)&g_down[(size_t)pos[k] * H_ + h];
        float wk = w[k];
        acc.x += wk * v.x; acc.y += wk * v.y;
        acc.z += wk * v.z; acc.w += wk * v.w;
    }
    *(float4*)&out[(size_t)t * H_ + h] = acc;
}

// ---------------- launch ----------------
extern "C" void kernel_launch(void* const* d_in, const int* in_sizes, int n_in,
                              void* d_out, int out_size) {
    const float* hidden = (const float*)d_in[0];
    const int*   tk_idx = (const int*)d_in[1];
    const float* tk_w   = (const float*)d_in[2];
    const float* gup    = (const float*)d_in[3];
    const float* dproj  = (const float*)d_in[4];
    float*       out    = (float*)d_out;

    uint16_t *xh, *xm, *gh, *gm, *dh, *dm, *ah, *am;
    float *down_p;
    cudaGetSymbolAddress((void**)&xh, q_xh); cudaGetSymbolAddress((void**)&xm, q_xm);
    cudaGetSymbolAddress((void**)&gh, q_gh); cudaGetSymbolAddress((void**)&gm, q_gm);
    cudaGetSymbolAddress((void**)&dh, q_dh); cudaGetSymbolAddress((void**)&dm, q_dm);
    cudaGetSymbolAddress((void**)&ah, q_ah); cudaGetSymbolAddress((void**)&am, q_am);
    cudaGetSymbolAddress((void**)&down_p, g_down);

    cudaFuncSetAttribute(gemm_pre<1>, cudaFuncAttributeMaxDynamicSharedMemorySize, GSMEM);
    cudaFuncSetAttribute(gemm_pre<0>, cudaFuncAttributeMaxDynamicSharedMemorySize, GSMEM);

    route_kernel<<<1, 1024>>>(tk_idx);
    split_kernel<<<(T_ * H_) / 1024, 256>>>(hidden, xh, xm);
    split_kernel<<<(E_ * 2 * I_ * H_) / 1024, 256>>>(gup, gh, gm);
    split_kernel<<<(E_ * H_ * I_) / 1024, 256>>>(dproj, dh, dm);

    gemm_pre<1><<<dim3(I_ / 64, TK_ / 128, E_), 256, GSMEM>>>(xh, xm, gh, gm, nullptr);
    gemm_pre<0><<<dim3(H_ / 128, TK_ / 128, E_), 256, GSMEM>>>(ah, am, dh, dm, down_p);
    combine_kernel<<<T_, 256>>>(tk_w, out);
}

// round 8
// speedup vs baseline: 2.0070x; 1.3825x over previous
#include <cuda_runtime.h>
#include <cuda_bf16.h>
#include <cstdint>
#include <math.h>

#define T_  1024
#define H_  1024
#define I_  1024
#define E_  16
#define K_  8
#define TK_ (T_ * K_)

// ---------------- scratch (no allocs allowed) ----------------
__device__ int   g_off[E_ + 1];
__device__ int   g_ptok[TK_];
__device__ int   g_pos[TK_];
__device__ float g_act[(size_t)TK_ * I_];     // 32 MB
__device__ float g_down[(size_t)TK_ * H_];    // 32 MB

// smem geometry: bf16x2-pair planes, 128 rows x 16 pairs, padded stride 20
#define LDP   20
#define PLANE (128 * LDP)        // u32 per plane
#define BUFU  (4 * PLANE)        // Ah, Am, Bh, Bm
#define GSMEM (2 * BUFU * 4)     // 81920 bytes (double buffer)

__device__ __forceinline__ float silu_f(float x) { return x / (1.0f + expf(-x)); }

__device__ __forceinline__ void mma_bf16(float* c, const uint32_t* a, const uint32_t* b) {
    asm volatile(
        "mma.sync.aligned.m16n8k16.row.col.f32.bf16.bf16.f32 "
        "{%0,%1,%2,%3}, {%4,%5,%6,%7}, {%8,%9}, {%0,%1,%2,%3};"
        : "+f"(c[0]), "+f"(c[1]), "+f"(c[2]), "+f"(c[3])
        : "r"(a[0]), "r"(a[1]), "r"(a[2]), "r"(a[3]), "r"(b[0]), "r"(b[1]));
}

__device__ __forceinline__ uint32_t b2u(__nv_bfloat162 v) {
    return *reinterpret_cast<uint32_t*>(&v);
}

// float4 -> 2 hi-pairs + 2 mid-pairs (bf16x2, low half = even k)
__device__ __forceinline__ void split_f4(float4 v, uint32_t& h0, uint32_t& h1,
                                         uint32_t& m0, uint32_t& m1) {
    __nv_bfloat162 a = __floats2bfloat162_rn(v.x, v.y);
    __nv_bfloat162 b = __floats2bfloat162_rn(v.z, v.w);
    float rx = v.x - __bfloat162float(a.x);
    float ry = v.y - __bfloat162float(a.y);
    float rz = v.z - __bfloat162float(b.x);
    float rw = v.w - __bfloat162float(b.y);
    __nv_bfloat162 c = __floats2bfloat162_rn(rx, ry);
    __nv_bfloat162 d = __floats2bfloat162_rn(rz, rw);
    h0 = b2u(a); h1 = b2u(b); m0 = b2u(c); m1 = b2u(d);
}

// ---------------- routing: stable chunked histogram ----------------
__global__ void route_kernel(const int* __restrict__ idx) {
    __shared__ int cnt[1024];
    __shared__ int off[1025];
    __shared__ int s_stride;
    int tid = threadIdx.x;
    if (tid == 0) {
        int nz = 0;
        #pragma unroll 1
        for (int j = 1; j < 256; j += 2) nz |= (idx[j] != 0);
        s_stride = nz ? 1 : 2;   // int32 vs int64 payload
    }
    __syncthreads();
    int stride = s_stride;
    int e = tid >> 6, c = tid & 63;
    int j0 = c * 128, j1 = j0 + 128;
    int cn = 0;
    for (int j = j0; j < j1; j++) cn += (idx[j * stride] == e);
    cnt[tid] = cn;
    __syncthreads();
    if (tid == 0) {
        int a = 0;
        for (int i = 0; i < 1024; i++) { off[i] = a; a += cnt[i]; }
        off[1024] = a;
        for (int ee = 0; ee <= E_; ee++) g_off[ee] = off[ee * 64];
    }
    __syncthreads();
    int p = off[tid];
    for (int j = j0; j < j1; j++) {
        if (idx[j * stride] == e) { g_ptok[p] = j >> 3; g_pos[j] = p; p++; }
    }
}

// ---------------------------------------------------------------------------
// Grouped GEMM, 3x bf16-split mma.sync m16n8k16. CTA tile 128(M)x128(N), BK=32.
// 512 threads, 16 warps (4m x 4n), warp tile 32x32 (mt=2, nt=4).
// FUSE=1 (GEMM1): A gathered from hidden, B rows = 64 gate + 64 up of i-block,
//                 epilogue computes silu(gate)*up -> g_act.
// FUSE=0 (GEMM2): A = g_act rows, B = down_proj, epilogue -> g_down.
// ---------------------------------------------------------------------------
template <int FUSE>
__global__ void __launch_bounds__(512, 1)
gemm_bf16(const float* __restrict__ A, const float* __restrict__ B,
          float* __restrict__ D) {
    int e    = blockIdx.z;
    int rbeg = g_off[e], rend = g_off[e + 1];
    int row0 = rbeg + blockIdx.y * 128;
    if (row0 >= rend) return;
    int n0 = blockIdx.x * (FUSE ? 64 : 128);   // i-block (FUSE) or h-block

    extern __shared__ uint32_t smem[];

    int tid  = threadIdx.x;
    int wid  = tid >> 5;
    int lane = tid & 31;
    int gid  = lane >> 2;
    int tig  = lane & 3;
    int wm   = (wid >> 2) * 32;   // 0,32,64,96
    int wn   = (wid & 3) * 32;    // 0,32,64,96

    // Global load mapping: 2 float4 per thread per matrix per K-tile (128x32 f32).
    const float* aptr[2];
    const float* bptr[2];
    int soff[2];
    #pragma unroll
    for (int j = 0; j < 2; j++) {
        int u = tid + 512 * j;
        int r = u >> 3, c4 = u & 7;
        int p = row0 + r; if (p >= rend) p = rend - 1;
        if (FUSE) aptr[j] = A + (size_t)g_ptok[p] * 1024 + c4 * 4;
        else      aptr[j] = A + (size_t)p * 1024 + c4 * 4;
        int br;
        if (FUSE) br = (r < 64) ? (n0 + r) : (I_ + n0 + r - 64);
        else      br = n0 + r;
        bptr[j] = B + ((size_t)e * (FUSE ? 2 * I_ : H_) + br) * 1024 + c4 * 4;
        soff[j] = r * LDP + c4 * 2;
    }

    float4 pa[2], pb[2];
    #pragma unroll
    for (int j = 0; j < 2; j++) { pa[j] = *(const float4*)aptr[j]; pb[j] = *(const float4*)bptr[j]; }

    // store tile 0 into buffer 0
    {
        uint32_t* Ah = smem;            uint32_t* Am = smem + PLANE;
        uint32_t* Bh = smem + 2*PLANE;  uint32_t* Bm = smem + 3*PLANE;
        #pragma unroll
        for (int j = 0; j < 2; j++) {
            uint32_t h0,h1,m0,m1;
            split_f4(pa[j], h0,h1,m0,m1);
            Ah[soff[j]] = h0; Ah[soff[j]+1] = h1; Am[soff[j]] = m0; Am[soff[j]+1] = m1;
            split_f4(pb[j], h0,h1,m0,m1);
            Bh[soff[j]] = h0; Bh[soff[j]+1] = h1; Bm[soff[j]] = m0; Bm[soff[j]+1] = m1;
        }
    }
    __syncthreads();

    float acc[2][4][4];
    #pragma unroll
    for (int mt = 0; mt < 2; mt++)
        #pragma unroll
        for (int nt = 0; nt < 4; nt++)
            #pragma unroll
            for (int q = 0; q < 4; q++) acc[mt][nt][q] = 0.f;

    for (int it = 0; it < 32; it++) {
        uint32_t* base = smem + (it & 1) * BUFU;
        uint32_t* Ah = base;            uint32_t* Am = base + PLANE;
        uint32_t* Bh = base + 2*PLANE;  uint32_t* Bm = base + 3*PLANE;

        // prefetch next K-tile into registers (latency hidden under MMAs)
        if (it < 31) {
            int k0 = (it + 1) * 32;
            #pragma unroll
            for (int j = 0; j < 2; j++) {
                pa[j] = *(const float4*)(aptr[j] + k0);
                pb[j] = *(const float4*)(bptr[j] + k0);
            }
        }

        #pragma unroll
        for (int kk = 0; kk < 2; kk++) {
            int po = kk * 8;  // pair offset within 16-pair row
            uint32_t ah[2][4], am[2][4];
            #pragma unroll
            for (int mt = 0; mt < 2; mt++) {
                int r = wm + mt * 16 + gid;
                int b0 = r * LDP + po + tig;
                int b1 = (r + 8) * LDP + po + tig;
                ah[mt][0] = Ah[b0];     ah[mt][1] = Ah[b1];
                ah[mt][2] = Ah[b0 + 4]; ah[mt][3] = Ah[b1 + 4];
                am[mt][0] = Am[b0];     am[mt][1] = Am[b1];
                am[mt][2] = Am[b0 + 4]; am[mt][3] = Am[b1 + 4];
            }
            uint32_t bh[4][2], bm[4][2];
            #pragma unroll
            for (int nt = 0; nt < 4; nt++) {
                int n = wn + nt * 8 + gid;
                int nb = n * LDP + po + tig;
                bh[nt][0] = Bh[nb]; bh[nt][1] = Bh[nb + 4];
                bm[nt][0] = Bm[nb]; bm[nt][1] = Bm[nb + 4];
            }
            #pragma unroll
            for (int nt = 0; nt < 4; nt++)
                #pragma unroll
                for (int mt = 0; mt < 2; mt++) {
                    mma_bf16(acc[mt][nt], ah[mt], bh[nt]);
                    mma_bf16(acc[mt][nt], ah[mt], bm[nt]);
                    mma_bf16(acc[mt][nt], am[mt], bh[nt]);
                }
        }

        // store prefetched tile into the other buffer
        if (it < 31) {
            uint32_t* nb = smem + ((it + 1) & 1) * BUFU;
            uint32_t* nAh = nb;            uint32_t* nAm = nb + PLANE;
            uint32_t* nBh = nb + 2*PLANE;  uint32_t* nBm = nb + 3*PLANE;
            #pragma unroll
            for (int j = 0; j < 2; j++) {
                uint32_t h0,h1,m0,m1;
                split_f4(pa[j], h0,h1,m0,m1);
                nAh[soff[j]] = h0; nAh[soff[j]+1] = h1; nAm[soff[j]] = m0; nAm[soff[j]+1] = m1;
                split_f4(pb[j], h0,h1,m0,m1);
                nBh[soff[j]] = h0; nBh[soff[j]+1] = h1; nBm[soff[j]] = m0; nBm[soff[j]+1] = m1;
            }
        }
        __syncthreads();
    }

    if (FUSE) {
        // recombine gate (cols 0..63) with up (cols 64..127) through smem
        float* s = (float*)smem;   // stride 132 floats, 128x128 tile (67.6 KB)
        #pragma unroll
        for (int mt = 0; mt < 2; mt++) {
            int r = wm + mt * 16 + gid;
            #pragma unroll
            for (int nt = 0; nt < 4; nt++) {
                int c = wn + nt * 8 + 2 * tig;
                *(float2*)&s[r * 132 + c]       = make_float2(acc[mt][nt][0], acc[mt][nt][1]);
                *(float2*)&s[(r + 8) * 132 + c] = make_float2(acc[mt][nt][2], acc[mt][nt][3]);
            }
        }
        __syncthreads();
        #pragma unroll
        for (int j = 0; j < 4; j++) {
            int u = tid + 512 * j;
            int r = u >> 4, cf = u & 15;
            int c = cf * 4;
            int p = row0 + r;
            if (p < rend) {
                float4 g = *(const float4*)&s[r * 132 + c];
                float4 up = *(const float4*)&s[r * 132 + 64 + c];
                float4 o;
                o.x = silu_f(g.x) * up.x; o.y = silu_f(g.y) * up.y;
                o.z = silu_f(g.z) * up.z; o.w = silu_f(g.w) * up.w;
                *(float4*)&D[(size_t)p * I_ + n0 + c] = o;
            }
        }
    } else {
        #pragma unroll
        for (int mt = 0; mt < 2; mt++) {
            int rr0 = row0 + wm + mt * 16 + gid;
            int rr1 = rr0 + 8;
            #pragma unroll
            for (int nt = 0; nt < 4; nt++) {
                int cc = n0 + wn + nt * 8 + 2 * tig;
                if (rr0 < rend)
                    *(float2*)&D[(size_t)rr0 * H_ + cc] = make_float2(acc[mt][nt][0], acc[mt][nt][1]);
                if (rr1 < rend)
                    *(float2*)&D[(size_t)rr1 * H_ + cc] = make_float2(acc[mt][nt][2], acc[mt][nt][3]);
            }
        }
    }
}

// ---------------- combine ----------------
__global__ void combine_kernel(const float* __restrict__ tw, float* __restrict__ out) {
    int t = blockIdx.x;
    __shared__ int   pos[K_];
    __shared__ float w[K_];
    if (threadIdx.x < K_) {
        pos[threadIdx.x] = g_pos[t * K_ + threadIdx.x];
        w[threadIdx.x]   = tw[t * K_ + threadIdx.x];
    }
    __syncthreads();
    int h = 4 * threadIdx.x;
    float4 acc = {0.f, 0.f, 0.f, 0.f};
    #pragma unroll
    for (int k = 0; k < K_; k++) {
        float4 v = *(const float4*)&g_down[(size_t)pos[k] * H_ + h];
        float wk = w[k];
        acc.x += wk * v.x; acc.y += wk * v.y;
        acc.z += wk * v.z; acc.w += wk * v.w;
    }
    *(float4*)&out[(size_t)t * H_ + h] = acc;
}

// ---------------- launch ----------------
extern "C" void kernel_launch(void* const* d_in, const int* in_sizes, int n_in,
                              void* d_out, int out_size) {
    const float* hidden = (const float*)d_in[0];
    const int*   tk_idx = (const int*)d_in[1];
    const float* tk_w   = (const float*)d_in[2];
    const float* gup    = (const float*)d_in[3];
    const float* dproj  = (const float*)d_in[4];
    float*       out    = (float*)d_out;

    float* act_p;  cudaGetSymbolAddress((void**)&act_p,  g_act);
    float* down_p; cudaGetSymbolAddress((void**)&down_p, g_down);

    cudaFuncSetAttribute(gemm_bf16<1>, cudaFuncAttributeMaxDynamicSharedMemorySize, GSMEM);
    cudaFuncSetAttribute(gemm_bf16<0>, cudaFuncAttributeMaxDynamicSharedMemorySize, GSMEM);

    route_kernel<<<1, 1024>>>(tk_idx);
    gemm_bf16<1><<<dim3(I_ / 64, TK_ / 128, E_), 512, GSMEM>>>(hidden, gup, act_p);
    gemm_bf16<0><<<dim3(H_ / 128, TK_ / 128, E_), 512, GSMEM>>>(act_p, dproj, down_p);
    combine_kernel<<<T_, 256>>>(tk_w, out);
}

// round 9
// speedup vs baseline: 2.4208x; 1.2062x over previous
#include <cuda_runtime.h>
#include <cuda_fp16.h>
#include <cstdint>
#include <math.h>

#define T_  1024
#define H_  1024
#define I_  1024
#define E_  16
#define K_  8
#define TK_ (T_ * K_)

// ---------------- scratch (no allocs allowed) ----------------
__device__ int   g_off[E_ + 1];
__device__ int   g_ptok[TK_];
__device__ int   g_pos[TK_];
__device__ float g_act[(size_t)TK_ * I_];     // 32 MB
__device__ float g_down[(size_t)TK_ * H_];    // 32 MB

// smem geometry: fp16x2-pair planes, 128 rows x 16 pairs, padded stride 20
#define LDP   20
#define PLANE (128 * LDP)        // u32 per plane
#define BUFU  (4 * PLANE)        // Ah, As, Bh, Bm
#define GSMEM (2 * BUFU * 4)     // 81920 bytes (double buffer)

#define SC_UP   1024.0f
#define SC_DN   (1.0f / 1024.0f)

__device__ __forceinline__ float silu_f(float x) { return x / (1.0f + expf(-x)); }

__device__ __forceinline__ void mma_f16(float* c, const uint32_t* a, const uint32_t* b) {
    asm volatile(
        "mma.sync.aligned.m16n8k16.row.col.f32.f16.f16.f32 "
        "{%0,%1,%2,%3}, {%4,%5,%6,%7}, {%8,%9}, {%0,%1,%2,%3};"
        : "+f"(c[0]), "+f"(c[1]), "+f"(c[2]), "+f"(c[3])
        : "r"(a[0]), "r"(a[1]), "r"(a[2]), "r"(a[3]), "r"(b[0]), "r"(b[1]));
}

__device__ __forceinline__ uint32_t h2u(__half2 v) {
    return *reinterpret_cast<uint32_t*>(&v);
}

// A: hi = fp16(a), scaled = fp16(a/1024)  (pairs, low half = even k)
__device__ __forceinline__ void splitA_f4(float4 v, uint32_t& h0, uint32_t& h1,
                                          uint32_t& s0, uint32_t& s1) {
    __half2 a = __floats2half2_rn(v.x, v.y);
    __half2 b = __floats2half2_rn(v.z, v.w);
    __half2 c = __floats2half2_rn(v.x * SC_DN, v.y * SC_DN);
    __half2 d = __floats2half2_rn(v.z * SC_DN, v.w * SC_DN);
    h0 = h2u(a); h1 = h2u(b); s0 = h2u(c); s1 = h2u(d);
}

// B: hi = fp16(b), mid = fp16((b - hi) * 1024)
__device__ __forceinline__ void splitB_f4(float4 v, uint32_t& h0, uint32_t& h1,
                                          uint32_t& m0, uint32_t& m1) {
    __half2 a = __floats2half2_rn(v.x, v.y);
    __half2 b = __floats2half2_rn(v.z, v.w);
    float rx = (v.x - __half2float(__low2half(a)))  * SC_UP;
    float ry = (v.y - __half2float(__high2half(a))) * SC_UP;
    float rz = (v.z - __half2float(__low2half(b)))  * SC_UP;
    float rw = (v.w - __half2float(__high2half(b))) * SC_UP;
    __half2 c = __floats2half2_rn(rx, ry);
    __half2 d = __floats2half2_rn(rz, rw);
    h0 = h2u(a); h1 = h2u(b); m0 = h2u(c); m1 = h2u(d);
}

// ---------------- routing: stable chunked histogram ----------------
__global__ void route_kernel(const int* __restrict__ idx) {
    __shared__ int cnt[1024];
    __shared__ int off[1025];
    __shared__ int s_stride;
    int tid = threadIdx.x;
    if (tid == 0) {
        int nz = 0;
        #pragma unroll 1
        for (int j = 1; j < 256; j += 2) nz |= (idx[j] != 0);
        s_stride = nz ? 1 : 2;   // int32 vs int64 payload
    }
    __syncthreads();
    int stride = s_stride;
    int e = tid >> 6, c = tid & 63;
    int j0 = c * 128, j1 = j0 + 128;
    int cn = 0;
    for (int j = j0; j < j1; j++) cn += (idx[j * stride] == e);
    cnt[tid] = cn;
    __syncthreads();
    if (tid == 0) {
        int a = 0;
        for (int i = 0; i < 1024; i++) { off[i] = a; a += cnt[i]; }
        off[1024] = a;
        for (int ee = 0; ee <= E_; ee++) g_off[ee] = off[ee * 64];
    }
    __syncthreads();
    int p = off[tid];
    for (int j = j0; j < j1; j++) {
        if (idx[j * stride] == e) { g_ptok[p] = j >> 3; g_pos[j] = p; p++; }
    }
}

// ---------------------------------------------------------------------------
// Grouped GEMM, 2-pass fp16 split mma.sync m16n8k16:
//   acc += ah*bh;  acc += as*bm      ( = a*b - (a-ah)*bh, err ~2.8e-4 RMS )
// CTA tile 128(M)x128(N), BK=32, 256 threads, 8 warps (4m x 2n), warp 32x64.
// FUSE=1 (GEMM1): A gathered from hidden, B rows = 64 gate + 64 up of i-block,
//                 epilogue computes silu(gate)*up -> g_act.
// FUSE=0 (GEMM2): A = g_act rows, B = down_proj, epilogue -> g_down.
// ---------------------------------------------------------------------------
template <int FUSE>
__global__ void __launch_bounds__(256, 1)
gemm_f16(const float* __restrict__ A, const float* __restrict__ B,
         float* __restrict__ D) {
    int e    = blockIdx.z;
    int rbeg = g_off[e], rend = g_off[e + 1];
    int row0 = rbeg + blockIdx.y * 128;
    if (row0 >= rend) return;
    int n0 = blockIdx.x * (FUSE ? 64 : 128);   // i-block (FUSE) or h-block

    extern __shared__ uint32_t smem[];

    int tid  = threadIdx.x;
    int wid  = tid >> 5;
    int lane = tid & 31;
    int gid  = lane >> 2;
    int tig  = lane & 3;
    int wm   = (wid >> 1) * 32;   // 0,32,64,96
    int wn   = (wid & 1) * 64;    // 0,64

    // Global load mapping: 4 float4 per thread per matrix per K-tile (128x32 f32).
    const float* aptr[4];
    const float* bptr[4];
    int soff[4];
    #pragma unroll
    for (int j = 0; j < 4; j++) {
        int u = tid + 256 * j;
        int r = u >> 3, c4 = u & 7;
        int p = row0 + r; if (p >= rend) p = rend - 1;
        if (FUSE) aptr[j] = A + (size_t)g_ptok[p] * 1024 + c4 * 4;
        else      aptr[j] = A + (size_t)p * 1024 + c4 * 4;
        int br;
        if (FUSE) br = (r < 64) ? (n0 + r) : (I_ + n0 + r - 64);
        else      br = n0 + r;
        bptr[j] = B + ((size_t)e * (FUSE ? 2 * I_ : H_) + br) * 1024 + c4 * 4;
        soff[j] = r * LDP + c4 * 2;
    }

    float4 pa[4], pb[4];
    #pragma unroll
    for (int j = 0; j < 4; j++) { pa[j] = *(const float4*)aptr[j]; pb[j] = *(const float4*)bptr[j]; }

    // store tile 0 into buffer 0
    {
        uint32_t* Ah = smem;            uint32_t* As = smem + PLANE;
        uint32_t* Bh = smem + 2*PLANE;  uint32_t* Bm = smem + 3*PLANE;
        #pragma unroll
        for (int j = 0; j < 4; j++) {
            uint32_t h0,h1,x0,x1;
            splitA_f4(pa[j], h0,h1,x0,x1);
            Ah[soff[j]] = h0; Ah[soff[j]+1] = h1; As[soff[j]] = x0; As[soff[j]+1] = x1;
            splitB_f4(pb[j], h0,h1,x0,x1);
            Bh[soff[j]] = h0; Bh[soff[j]+1] = h1; Bm[soff[j]] = x0; Bm[soff[j]+1] = x1;
        }
    }
    __syncthreads();

    float acc[2][8][4];
    #pragma unroll
    for (int mt = 0; mt < 2; mt++)
        #pragma unroll
        for (int nt = 0; nt < 8; nt++)
            #pragma unroll
            for (int q = 0; q < 4; q++) acc[mt][nt][q] = 0.f;

    for (int it = 0; it < 32; it++) {
        uint32_t* base = smem + (it & 1) * BUFU;
        uint32_t* Ah = base;            uint32_t* As = base + PLANE;
        uint32_t* Bh = base + 2*PLANE;  uint32_t* Bm = base + 3*PLANE;

        // prefetch next K-tile into registers (latency hidden under MMAs)
        if (it < 31) {
            int k0 = (it + 1) * 32;
            #pragma unroll
            for (int j = 0; j < 4; j++) {
                pa[j] = *(const float4*)(aptr[j] + k0);
                pb[j] = *(const float4*)(bptr[j] + k0);
            }
        }

        #pragma unroll
        for (int kk = 0; kk < 2; kk++) {
            int po = kk * 8;  // pair offset within 16-pair row
            uint32_t ah[2][4], as[2][4];
            #pragma unroll
            for (int mt = 0; mt < 2; mt++) {
                int r = wm + mt * 16 + gid;
                int b0 = r * LDP + po + tig;
                int b1 = (r + 8) * LDP + po + tig;
                ah[mt][0] = Ah[b0];     ah[mt][1] = Ah[b1];
                ah[mt][2] = Ah[b0 + 4]; ah[mt][3] = Ah[b1 + 4];
                as[mt][0] = As[b0];     as[mt][1] = As[b1];
                as[mt][2] = As[b0 + 4]; as[mt][3] = As[b1 + 4];
            }
            uint32_t bh[8][2], bm[8][2];
            #pragma unroll
            for (int nt = 0; nt < 8; nt++) {
                int n = wn + nt * 8 + gid;
                int nb = n * LDP + po + tig;
                bh[nt][0] = Bh[nb]; bh[nt][1] = Bh[nb + 4];
                bm[nt][0] = Bm[nb]; bm[nt][1] = Bm[nb + 4];
            }
            #pragma unroll
            for (int nt = 0; nt < 8; nt++)
                #pragma unroll
                for (int mt = 0; mt < 2; mt++) {
                    mma_f16(acc[mt][nt], ah[mt], bh[nt]);
                    mma_f16(acc[mt][nt], as[mt], bm[nt]);
                }
        }

        // store prefetched tile into the other buffer
        if (it < 31) {
            uint32_t* nb = smem + ((it + 1) & 1) * BUFU;
            uint32_t* nAh = nb;            uint32_t* nAs = nb + PLANE;
            uint32_t* nBh = nb + 2*PLANE;  uint32_t* nBm = nb + 3*PLANE;
            #pragma unroll
            for (int j = 0; j < 4; j++) {
                uint32_t h0,h1,x0,x1;
                splitA_f4(pa[j], h0,h1,x0,x1);
                nAh[soff[j]] = h0; nAh[soff[j]+1] = h1; nAs[soff[j]] = x0; nAs[soff[j]+1] = x1;
                splitB_f4(pb[j], h0,h1,x0,x1);
                nBh[soff[j]] = h0; nBh[soff[j]+1] = h1; nBm[soff[j]] = x0; nBm[soff[j]+1] = x1;
            }
        }
        __syncthreads();
    }

    if (FUSE) {
        // recombine gate (cols 0..63) with up (cols 64..127) through smem
        float* s = (float*)smem;   // stride 132 floats, 128x128 tile (67.6 KB)
        #pragma unroll
        for (int mt = 0; mt < 2; mt++) {
            int r = wm + mt * 16 + gid;
            #pragma unroll
            for (int nt = 0; nt < 8; nt++) {
                int c = wn + nt * 8 + 2 * tig;
                *(float2*)&s[r * 132 + c]       = make_float2(acc[mt][nt][0], acc[mt][nt][1]);
                *(float2*)&s[(r + 8) * 132 + c] = make_float2(acc[mt][nt][2], acc[mt][nt][3]);
            }
        }
        __syncthreads();
        #pragma unroll
        for (int j = 0; j < 8; j++) {
            int u = tid + 256 * j;
            int r = u >> 4, cf = u & 15;
            int c = cf * 4;
            int p = row0 + r;
            if (p < rend) {
                float4 g = *(const float4*)&s[r * 132 + c];
                float4 up = *(const float4*)&s[r * 132 + 64 + c];
                float4 o;
                o.x = silu_f(g.x) * up.x; o.y = silu_f(g.y) * up.y;
                o.z = silu_f(g.z) * up.z; o.w = silu_f(g.w) * up.w;
                *(float4*)&D[(size_t)p * I_ + n0 + c] = o;
            }
        }
    } else {
        #pragma unroll
        for (int mt = 0; mt < 2; mt++) {
            int rr0 = row0 + wm + mt * 16 + gid;
            int rr1 = rr0 + 8;
            #pragma unroll
            for (int nt = 0; nt < 8; nt++) {
                int cc = n0 + wn + nt * 8 + 2 * tig;
                if (rr0 < rend)
                    *(float2*)&D[(size_t)rr0 * H_ + cc] = make_float2(acc[mt][nt][0], acc[mt][nt][1]);
                if (rr1 < rend)
                    *(float2*)&D[(size_t)rr1 * H_ + cc] = make_float2(acc[mt][nt][2], acc[mt][nt][3]);
            }
        }
    }
}

// ---------------- combine ----------------
__global__ void combine_kernel(const float* __restrict__ tw, float* __restrict__ out) {
    int t = blockIdx.x;
    __shared__ int   pos[K_];
    __shared__ float w[K_];
    if (threadIdx.x < K_) {
        pos[threadIdx.x] = g_pos[t * K_ + threadIdx.x];
        w[threadIdx.x]   = tw[t * K_ + threadIdx.x];
    }
    __syncthreads();
    int h = 4 * threadIdx.x;
    float4 acc = {0.f, 0.f, 0.f, 0.f};
    #pragma unroll
    for (int k = 0; k < K_; k++) {
        float4 v = *(const float4*)&g_down[(size_t)pos[k] * H_ + h];
        float wk = w[k];
        acc.x += wk * v.x; acc.y += wk * v.y;
        acc.z += wk * v.z; acc.w += wk * v.w;
    }
    *(float4*)&out[(size_t)t * H_ + h] = acc;
}

// ---------------- launch ----------------
extern "C" void kernel_launch(void* const* d_in, const int* in_sizes, int n_in,
                              void* d_out, int out_size) {
    const float* hidden = (const float*)d_in[0];
    const int*   tk_idx = (const int*)d_in[1];
    const float* tk_w   = (const float*)d_in[2];
    const float* gup    = (const float*)d_in[3];
    const float* dproj  = (const float*)d_in[4];
    float*       out    = (float*)d_out;

    float* act_p;  cudaGetSymbolAddress((void**)&act_p,  g_act);
    float* down_p; cudaGetSymbolAddress((void**)&down_p, g_down);

    cudaFuncSetAttribute(gemm_f16<1>, cudaFuncAttributeMaxDynamicSharedMemorySize, GSMEM);
    cudaFuncSetAttribute(gemm_f16<0>, cudaFuncAttributeMaxDynamicSharedMemorySize, GSMEM);

    route_kernel<<<1, 1024>>>(tk_idx);
    gemm_f16<1><<<dim3(I_ / 64, TK_ / 128, E_), 256, GSMEM>>>(hidden, gup, act_p);
    gemm_f16<0><<<dim3(H_ / 128, TK_ / 128, E_), 256, GSMEM>>>(act_p, dproj, down_p);
    combine_kernel<<<T_, 256>>>(tk_w, out);
}

// round 10
// speedup vs baseline: 2.5020x; 1.0336x over previous
#include <cuda_runtime.h>
#include <cuda_fp16.h>
#include <cstdint>
#include <math.h>

#define T_  1024
#define H_  1024
#define I_  1024
#define E_  16
#define K_  8
#define TK_ (T_ * K_)

// ---------------- scratch (no allocs allowed) ----------------
__device__ int   g_off[E_ + 1];
__device__ int   g_ptok[TK_];
__device__ int   g_pos[TK_];
__device__ float g_act[(size_t)TK_ * I_];     // 32 MB
__device__ float g_down[(size_t)TK_ * H_];    // 32 MB

// smem geometry: linear-k fp16 planes, 128 rows x 64B data, 80B pitch
#define PITCHB 80
#define PLB    (128 * PITCHB)    // 10240 B per plane
#define STGB   (4 * PLB)         // Ah, As, Bh, Bm = 40960 B per stage
#define GSMEM  (2 * STGB)        // 81920 B (double buffer)

#define SC_UP   1024.0f
#define SC_DN   (1.0f / 1024.0f)

__device__ __forceinline__ uint32_t smem_u32(const void* p) {
    uint32_t a;
    asm("{ .reg .u64 t; cvta.to.shared.u64 t, %1; cvt.u32.u64 %0, t; }" : "=r"(a) : "l"(p));
    return a;
}
__device__ __forceinline__ float silu_f(float x) { return x / (1.0f + expf(-x)); }

__device__ __forceinline__ void mma_f16(float* c, const uint32_t* a, const uint32_t* b) {
    asm volatile(
        "mma.sync.aligned.m16n8k16.row.col.f32.f16.f16.f32 "
        "{%0,%1,%2,%3}, {%4,%5,%6,%7}, {%8,%9}, {%0,%1,%2,%3};"
        : "+f"(c[0]), "+f"(c[1]), "+f"(c[2]), "+f"(c[3])
        : "r"(a[0]), "r"(a[1]), "r"(a[2]), "r"(a[3]), "r"(b[0]), "r"(b[1]));
}
__device__ __forceinline__ void ldsm4(uint32_t* d, uint32_t addr) {
    asm volatile("ldmatrix.sync.aligned.m8n8.x4.shared.b16 {%0,%1,%2,%3}, [%4];"
        : "=r"(d[0]), "=r"(d[1]), "=r"(d[2]), "=r"(d[3]) : "r"(addr));
}
__device__ __forceinline__ uint32_t h2u(__half2 v) {
    return *reinterpret_cast<uint32_t*>(&v);
}

// A: hi = fp16(a), scaled = fp16(a/1024)  (u32 = halves k,k+1 little-endian)
__device__ __forceinline__ void splitA_f4(float4 v, uint32_t& h0, uint32_t& h1,
                                          uint32_t& s0, uint32_t& s1) {
    __half2 a = __floats2half2_rn(v.x, v.y);
    __half2 b = __floats2half2_rn(v.z, v.w);
    __half2 c = __floats2half2_rn(v.x * SC_DN, v.y * SC_DN);
    __half2 d = __floats2half2_rn(v.z * SC_DN, v.w * SC_DN);
    h0 = h2u(a); h1 = h2u(b); s0 = h2u(c); s1 = h2u(d);
}

// B: hi = fp16(b), mid = fp16((b - hi) * 1024)
__device__ __forceinline__ void splitB_f4(float4 v, uint32_t& h0, uint32_t& h1,
                                          uint32_t& m0, uint32_t& m1) {
    __half2 a = __floats2half2_rn(v.x, v.y);
    __half2 b = __floats2half2_rn(v.z, v.w);
    float rx = (v.x - __half2float(__low2half(a)))  * SC_UP;
    float ry = (v.y - __half2float(__high2half(a))) * SC_UP;
    float rz = (v.z - __half2float(__low2half(b)))  * SC_UP;
    float rw = (v.w - __half2float(__high2half(b))) * SC_UP;
    __half2 c = __floats2half2_rn(rx, ry);
    __half2 d = __floats2half2_rn(rz, rw);
    h0 = h2u(a); h1 = h2u(b); m0 = h2u(c); m1 = h2u(d);
}

// ---------------- routing: stable chunked histogram ----------------
__global__ void route_kernel(const int* __restrict__ idx) {
    __shared__ int cnt[1024];
    __shared__ int off[1025];
    __shared__ int s_stride;
    int tid = threadIdx.x;
    if (tid == 0) {
        int nz = 0;
        #pragma unroll 1
        for (int j = 1; j < 256; j += 2) nz |= (idx[j] != 0);
        s_stride = nz ? 1 : 2;   // int32 vs int64 payload
    }
    __syncthreads();
    int stride = s_stride;
    int e = tid >> 6, c = tid & 63;
    int j0 = c * 128, j1 = j0 + 128;
    int cn = 0;
    for (int j = j0; j < j1; j++) cn += (idx[j * stride] == e);
    cnt[tid] = cn;
    __syncthreads();
    if (tid == 0) {
        int a = 0;
        for (int i = 0; i < 1024; i++) { off[i] = a; a += cnt[i]; }
        off[1024] = a;
        for (int ee = 0; ee <= E_; ee++) g_off[ee] = off[ee * 64];
    }
    __syncthreads();
    int p = off[tid];
    for (int j = j0; j < j1; j++) {
        if (idx[j * stride] == e) { g_ptok[p] = j >> 3; g_pos[j] = p; p++; }
    }
}

// ---------------------------------------------------------------------------
// Grouped GEMM, 2-pass fp16 split mma.sync m16n8k16 (acc += ah*bh + as*bm).
// CTA tile 128(M)x128(N), BK=32, 256 threads, 8 warps (4m x 2n), warp 32x64.
// ldmatrix.x4 fragment loads on 80B-pitch linear-k planes (R6-verified layout).
// FUSE=1 (GEMM1): A gathered from hidden, B rows = 64 gate + 64 up of i-block,
//                 epilogue computes silu(gate)*up -> g_act.
// FUSE=0 (GEMM2): A = g_act rows, B = down_proj, epilogue -> g_down.
// ---------------------------------------------------------------------------
template <int FUSE>
__global__ void __launch_bounds__(256, 1)
gemm_f16(const float* __restrict__ A, const float* __restrict__ B,
         float* __restrict__ D) {
    int e    = blockIdx.z;
    int rbeg = g_off[e], rend = g_off[e + 1];
    int row0 = rbeg + blockIdx.y * 128;
    if (row0 >= rend) return;
    int n0 = blockIdx.x * (FUSE ? 64 : 128);   // i-block (FUSE) or h-block

    extern __shared__ char smem[];
    uint32_t sb = smem_u32(smem);

    int tid  = threadIdx.x;
    int wid  = tid >> 5;
    int lane = tid & 31;
    int gid  = lane >> 2;
    int tig  = lane & 3;
    int wm   = (wid >> 1) * 32;   // 0,32,64,96
    int wn   = (wid & 1) * 64;    // 0,64

    // Global load mapping: 4 float4 per thread per matrix per K-tile (128x32 f32).
    const float* aptr[4];
    const float* bptr[4];
    int soff[4];   // byte offset within a plane
    #pragma unroll
    for (int j = 0; j < 4; j++) {
        int u = tid + 256 * j;
        int r = u >> 3, c4 = u & 7;
        int p = row0 + r; if (p >= rend) p = rend - 1;
        if (FUSE) aptr[j] = A + (size_t)g_ptok[p] * 1024 + c4 * 4;
        else      aptr[j] = A + (size_t)p * 1024 + c4 * 4;
        int br;
        if (FUSE) br = (r < 64) ? (n0 + r) : (I_ + n0 + r - 64);
        else      br = n0 + r;
        bptr[j] = B + ((size_t)e * (FUSE ? 2 * I_ : H_) + br) * 1024 + c4 * 4;
        soff[j] = r * PITCHB + c4 * 8;
    }

    float4 pa[4], pb[4];
    #pragma unroll
    for (int j = 0; j < 4; j++) { pa[j] = *(const float4*)aptr[j]; pb[j] = *(const float4*)bptr[j]; }

    // store tile 0 into buffer 0
    #pragma unroll
    for (int j = 0; j < 4; j++) {
        uint32_t h0,h1,x0,x1;
        splitA_f4(pa[j], h0,h1,x0,x1);
        *(uint2*)(smem + soff[j])       = make_uint2(h0, h1);
        *(uint2*)(smem + PLB + soff[j]) = make_uint2(x0, x1);
        splitB_f4(pb[j], h0,h1,x0,x1);
        *(uint2*)(smem + 2*PLB + soff[j]) = make_uint2(h0, h1);
        *(uint2*)(smem + 3*PLB + soff[j]) = make_uint2(x0, x1);
    }
    __syncthreads();

    float acc[2][8][4];
    #pragma unroll
    for (int mt = 0; mt < 2; mt++)
        #pragma unroll
        for (int nt = 0; nt < 8; nt++)
            #pragma unroll
            for (int q = 0; q < 4; q++) acc[mt][nt][q] = 0.f;

    // ldmatrix lane offsets (R6-verified)
    uint32_t aoff = (uint32_t)((((lane >> 3) & 1) * 8 + (lane & 7)) * PITCHB + (lane >> 4) * 16);
    uint32_t boff = (uint32_t)(((lane >> 4) * 8 + (lane & 7)) * PITCHB + ((lane >> 3) & 1) * 16);

    for (int it = 0; it < 32; it++) {
        uint32_t bb = sb + (it & 1) * STGB;

        // prefetch next K-tile into registers (latency hidden under MMAs)
        if (it < 31) {
            int k0 = (it + 1) * 32;
            #pragma unroll
            for (int j = 0; j < 4; j++) {
                pa[j] = *(const float4*)(aptr[j] + k0);
                pb[j] = *(const float4*)(bptr[j] + k0);
            }
        }

        #pragma unroll
        for (int ks = 0; ks < 2; ks++) {
            uint32_t kb = ks * 32;   // 16 halves = 32 bytes per k16 step
            uint32_t ah[2][4], as[2][4];
            #pragma unroll
            for (int mt = 0; mt < 2; mt++) {
                uint32_t ad = bb + (wm + mt * 16) * PITCHB + kb + aoff;
                ldsm4(ah[mt], ad);
                ldsm4(as[mt], ad + PLB);
            }
            uint32_t bh[8][2], bm[8][2];
            #pragma unroll
            for (int np = 0; np < 4; np++) {
                uint32_t r4[4], s4[4];
                uint32_t bd = bb + 2 * PLB + (wn + np * 16) * PITCHB + kb + boff;
                ldsm4(r4, bd);
                ldsm4(s4, bd + PLB);
                bh[2*np][0] = r4[0];   bh[2*np][1] = r4[1];
                bh[2*np+1][0] = r4[2]; bh[2*np+1][1] = r4[3];
                bm[2*np][0] = s4[0];   bm[2*np][1] = s4[1];
                bm[2*np+1][0] = s4[2]; bm[2*np+1][1] = s4[3];
            }
            #pragma unroll
            for (int nt = 0; nt < 8; nt++)
                #pragma unroll
                for (int mt = 0; mt < 2; mt++) {
                    mma_f16(acc[mt][nt], ah[mt], bh[nt]);
                    mma_f16(acc[mt][nt], as[mt], bm[nt]);
                }
        }

        // store prefetched tile into the other buffer
        if (it < 31) {
            char* nb = smem + ((it + 1) & 1) * STGB;
            #pragma unroll
            for (int j = 0; j < 4; j++) {
                uint32_t h0,h1,x0,x1;
                splitA_f4(pa[j], h0,h1,x0,x1);
                *(uint2*)(nb + soff[j])       = make_uint2(h0, h1);
                *(uint2*)(nb + PLB + soff[j]) = make_uint2(x0, x1);
                splitB_f4(pb[j], h0,h1,x0,x1);
                *(uint2*)(nb + 2*PLB + soff[j]) = make_uint2(h0, h1);
                *(uint2*)(nb + 3*PLB + soff[j]) = make_uint2(x0, x1);
            }
        }
        __syncthreads();
    }

    if (FUSE) {
        // recombine gate (cols 0..63) with up (cols 64..127) through smem
        float* s = (float*)smem;   // stride 132 floats, 128x128 tile (67.6 KB)
        #pragma unroll
        for (int mt = 0; mt < 2; mt++) {
            int r = wm + mt * 16 + gid;
            #pragma unroll
            for (int nt = 0; nt < 8; nt++) {
                int c = wn + nt * 8 + 2 * tig;
                *(float2*)&s[r * 132 + c]       = make_float2(acc[mt][nt][0], acc[mt][nt][1]);
                *(float2*)&s[(r + 8) * 132 + c] = make_float2(acc[mt][nt][2], acc[mt][nt][3]);
            }
        }
        __syncthreads();
        #pragma unroll
        for (int j = 0; j < 8; j++) {
            int u = tid + 256 * j;
            int r = u >> 4, cf = u & 15;
            int c = cf * 4;
            int p = row0 + r;
            if (p < rend) {
                float4 g = *(const float4*)&s[r * 132 + c];
                float4 up = *(const float4*)&s[r * 132 + 64 + c];
                float4 o;
                o.x = silu_f(g.x) * up.x; o.y = silu_f(g.y) * up.y;
                o.z = silu_f(g.z) * up.z; o.w = silu_f(g.w) * up.w;
                *(float4*)&D[(size_t)p * I_ + n0 + c] = o;
            }
        }
    } else {
        #pragma unroll
        for (int mt = 0; mt < 2; mt++) {
            int rr0 = row0 + wm + mt * 16 + gid;
            int rr1 = rr0 + 8;
            #pragma unroll
            for (int nt = 0; nt < 8; nt++) {
                int cc = n0 + wn + nt * 8 + 2 * tig;
                if (rr0 < rend)
                    *(float2*)&D[(size_t)rr0 * H_ + cc] = make_float2(acc[mt][nt][0], acc[mt][nt][1]);
                if (rr1 < rend)
                    *(float2*)&D[(size_t)rr1 * H_ + cc] = make_float2(acc[mt][nt][2], acc[mt][nt][3]);
            }
        }
    }
}

// ---------------- combine ----------------
__global__ void combine_kernel(const float* __restrict__ tw, float* __restrict__ out) {
    int t = blockIdx.x;
    __shared__ int   pos[K_];
    __shared__ float w[K_];
    if (threadIdx.x < K_) {
        pos[threadIdx.x] = g_pos[t * K_ + threadIdx.x];
        w[threadIdx.x]   = tw[t * K_ + threadIdx.x];
    }
    __syncthreads();
    int h = 4 * threadIdx.x;
    float4 acc = {0.f, 0.f, 0.f, 0.f};
    #pragma unroll
    for (int k = 0; k < K_; k++) {
        float4 v = *(const float4*)&g_down[(size_t)pos[k] * H_ + h];
        float wk = w[k];
        acc.x += wk * v.x; acc.y += wk * v.y;
        acc.z += wk * v.z; acc.w += wk * v.w;
    }
    *(float4*)&out[(size_t)t * H_ + h] = acc;
}

// ---------------- launch ----------------
extern "C" void kernel_launch(void* const* d_in, const int* in_sizes, int n_in,
                              void* d_out, int out_size) {
    const float* hidden = (const float*)d_in[0];
    const int*   tk_idx = (const int*)d_in[1];
    const float* tk_w   = (const float*)d_in[2];
    const float* gup    = (const float*)d_in[3];
    const float* dproj  = (const float*)d_in[4];
    float*       out    = (float*)d_out;

    float* act_p;  cudaGetSymbolAddress((void**)&act_p,  g_act);
    float* down_p; cudaGetSymbolAddress((void**)&down_p, g_down);

    cudaFuncSetAttribute(gemm_f16<1>, cudaFuncAttributeMaxDynamicSharedMemorySize, GSMEM);
    cudaFuncSetAttribute(gemm_f16<0>, cudaFuncAttributeMaxDynamicSharedMemorySize, GSMEM);

    route_kernel<<<1, 1024>>>(tk_idx);
    gemm_f16<1><<<dim3(I_ / 64, TK_ / 128, E_), 256, GSMEM>>>(hidden, gup, act_p);
    gemm_f16<0><<<dim3(H_ / 128, TK_ / 128, E_), 256, GSMEM>>>(act_p, dproj, down_p);
    combine_kernel<<<T_, 256>>>(tk_w, out);
}

// round 11
// speedup vs baseline: 3.4111x; 1.3634x over previous
#include <cuda_runtime.h>
#include <cuda_fp16.h>
#include <cstdint>
#include <math.h>

#define T_  1024
#define H_  1024
#define I_  1024
#define E_  16
#define K_  8
#define TK_ (T_ * K_)

// ---------------- scratch (no allocs allowed) ----------------
__device__ int   g_off[E_ + 1];
__device__ int   g_ptok[TK_];
__device__ int   g_pos[TK_];
__device__ float g_act[(size_t)TK_ * I_];     // 32 MB
__device__ float g_down[(size_t)TK_ * H_];    // 32 MB

// smem geometry: linear-k fp16 planes, 128 rows x 64B data, 80B pitch
#define PITCHB 80
#define PLB    (128 * PITCHB)    // 10240 B per plane
#define STGB   (2 * PLB)         // Ah, Bh = 20480 B per stage
#define GSMEM  (2 * STGB)        // 40960 B (double buffer)
#define GSMEM_FUSE 69632         // FUSE epilogue staging: 128*132*4 = 67584

__device__ __forceinline__ uint32_t smem_u32(const void* p) {
    uint32_t a;
    asm("{ .reg .u64 t; cvta.to.shared.u64 t, %1; cvt.u32.u64 %0, t; }" : "=r"(a) : "l"(p));
    return a;
}
__device__ __forceinline__ float silu_f(float x) { return x / (1.0f + expf(-x)); }

__device__ __forceinline__ void mma_f16(float* c, const uint32_t* a, const uint32_t* b) {
    asm volatile(
        "mma.sync.aligned.m16n8k16.row.col.f32.f16.f16.f32 "
        "{%0,%1,%2,%3}, {%4,%5,%6,%7}, {%8,%9}, {%0,%1,%2,%3};"
        : "+f"(c[0]), "+f"(c[1]), "+f"(c[2]), "+f"(c[3])
        : "r"(a[0]), "r"(a[1]), "r"(a[2]), "r"(a[3]), "r"(b[0]), "r"(b[1]));
}
__device__ __forceinline__ void ldsm4(uint32_t* d, uint32_t addr) {
    asm volatile("ldmatrix.sync.aligned.m8n8.x4.shared.b16 {%0,%1,%2,%3}, [%4];"
        : "=r"(d[0]), "=r"(d[1]), "=r"(d[2]), "=r"(d[3]) : "r"(addr));
}
__device__ __forceinline__ uint32_t h2u(__half2 v) {
    return *reinterpret_cast<uint32_t*>(&v);
}
// float4 -> 2 fp16x2 words (halves k, k+1 little-endian)
__device__ __forceinline__ void cvt_f4(float4 v, uint32_t& h0, uint32_t& h1) {
    h0 = h2u(__floats2half2_rn(v.x, v.y));
    h1 = h2u(__floats2half2_rn(v.z, v.w));
}

// ---------------- routing: stable chunked histogram ----------------
__global__ void route_kernel(const int* __restrict__ idx) {
    __shared__ int cnt[1024];
    __shared__ int off[1025];
    __shared__ int s_stride;
    int tid = threadIdx.x;
    if (tid == 0) {
        int nz = 0;
        #pragma unroll 1
        for (int j = 1; j < 256; j += 2) nz |= (idx[j] != 0);
        s_stride = nz ? 1 : 2;   // int32 vs int64 payload
    }
    __syncthreads();
    int stride = s_stride;
    int e = tid >> 6, c = tid & 63;
    int j0 = c * 128, j1 = j0 + 128;
    int cn = 0;
    for (int j = j0; j < j1; j++) cn += (idx[j * stride] == e);
    cnt[tid] = cn;
    __syncthreads();
    if (tid == 0) {
        int a = 0;
        for (int i = 0; i < 1024; i++) { off[i] = a; a += cnt[i]; }
        off[1024] = a;
        for (int ee = 0; ee <= E_; ee++) g_off[ee] = off[ee * 64];
    }
    __syncthreads();
    int p = off[tid];
    for (int j = j0; j < j1; j++) {
        if (idx[j * stride] == e) { g_ptok[p] = j >> 3; g_pos[j] = p; p++; }
    }
}

// ---------------------------------------------------------------------------
// Grouped GEMM, 1-pass fp16 mma.sync m16n8k16 (acc += ah*bh; ~5e-4 rel err).
// CTA tile 128(M)x128(N), BK=32, 256 threads, 8 warps (4m x 2n), warp 32x64.
// ldmatrix.x4 fragments on 80B-pitch linear-k planes (R10-verified layout).
// Double-buffered smem (2x20KB) -> target 2 CTAs/SM to hide split/sync phases.
// FUSE=1 (GEMM1): A gathered from hidden, B rows = 64 gate + 64 up of i-block,
//                 epilogue computes silu(gate)*up -> g_act.
// FUSE=0 (GEMM2): A = g_act rows, B = down_proj, epilogue -> g_down.
// ---------------------------------------------------------------------------
template <int FUSE>
__global__ void __launch_bounds__(256, 2)
gemm_f16(const float* __restrict__ A, const float* __restrict__ B,
         float* __restrict__ D) {
    int e    = blockIdx.z;
    int rbeg = g_off[e], rend = g_off[e + 1];
    int row0 = rbeg + blockIdx.y * 128;
    if (row0 >= rend) return;
    int n0 = blockIdx.x * (FUSE ? 64 : 128);   // i-block (FUSE) or h-block

    extern __shared__ char smem[];
    uint32_t sb = smem_u32(smem);

    int tid  = threadIdx.x;
    int wid  = tid >> 5;
    int lane = tid & 31;
    int gid  = lane >> 2;
    int tig  = lane & 3;
    int wm   = (wid >> 1) * 32;   // 0,32,64,96
    int wn   = (wid & 1) * 64;    // 0,64

    // Global load mapping: 4 float4 per thread per matrix per K-tile (128x32 f32).
    const float* aptr[4];
    const float* bptr[4];
    int soff[4];   // byte offset within a plane
    #pragma unroll
    for (int j = 0; j < 4; j++) {
        int u = tid + 256 * j;
        int r = u >> 3, c4 = u & 7;
        int p = row0 + r; if (p >= rend) p = rend - 1;
        if (FUSE) aptr[j] = A + (size_t)g_ptok[p] * 1024 + c4 * 4;
        else      aptr[j] = A + (size_t)p * 1024 + c4 * 4;
        int br;
        if (FUSE) br = (r < 64) ? (n0 + r) : (I_ + n0 + r - 64);
        else      br = n0 + r;
        bptr[j] = B + ((size_t)e * (FUSE ? 2 * I_ : H_) + br) * 1024 + c4 * 4;
        soff[j] = r * PITCHB + c4 * 8;
    }

    // prefetch tile 0, convert to fp16 pairs immediately (low reg footprint)
    uint32_t pa[4][2], pb[4][2];
    #pragma unroll
    for (int j = 0; j < 4; j++) {
        cvt_f4(*(const float4*)aptr[j], pa[j][0], pa[j][1]);
        cvt_f4(*(const float4*)bptr[j], pb[j][0], pb[j][1]);
    }
    // store tile 0 into buffer 0
    #pragma unroll
    for (int j = 0; j < 4; j++) {
        *(uint2*)(smem + soff[j])       = make_uint2(pa[j][0], pa[j][1]);
        *(uint2*)(smem + PLB + soff[j]) = make_uint2(pb[j][0], pb[j][1]);
    }
    __syncthreads();

    float acc[2][8][4];
    #pragma unroll
    for (int mt = 0; mt < 2; mt++)
        #pragma unroll
        for (int nt = 0; nt < 8; nt++)
            #pragma unroll
            for (int q = 0; q < 4; q++) acc[mt][nt][q] = 0.f;

    // ldmatrix lane offsets (R10-verified)
    uint32_t aoff = (uint32_t)((((lane >> 3) & 1) * 8 + (lane & 7)) * PITCHB + (lane >> 4) * 16);
    uint32_t boff = (uint32_t)(((lane >> 4) * 8 + (lane & 7)) * PITCHB + ((lane >> 3) & 1) * 16);

    for (int it = 0; it < 32; it++) {
        uint32_t bb = sb + (it & 1) * STGB;

        // prefetch + convert next K-tile (latency hidden under MMAs)
        if (it < 31) {
            int k0 = (it + 1) * 32;
            #pragma unroll
            for (int j = 0; j < 4; j++) {
                cvt_f4(*(const float4*)(aptr[j] + k0), pa[j][0], pa[j][1]);
                cvt_f4(*(const float4*)(bptr[j] + k0), pb[j][0], pb[j][1]);
            }
        }

        #pragma unroll
        for (int ks = 0; ks < 2; ks++) {
            uint32_t kb = ks * 32;   // 16 halves = 32 bytes per k16 step
            uint32_t ah[2][4];
            #pragma unroll
            for (int mt = 0; mt < 2; mt++)
                ldsm4(ah[mt], bb + (wm + mt * 16) * PITCHB + kb + aoff);
            uint32_t bh[8][2];
            #pragma unroll
            for (int np = 0; np < 4; np++) {
                uint32_t r4[4];
                ldsm4(r4, bb + PLB + (wn + np * 16) * PITCHB + kb + boff);
                bh[2*np][0] = r4[0];   bh[2*np][1] = r4[1];
                bh[2*np+1][0] = r4[2]; bh[2*np+1][1] = r4[3];
            }
            #pragma unroll
            for (int nt = 0; nt < 8; nt++)
                #pragma unroll
                for (int mt = 0; mt < 2; mt++)
                    mma_f16(acc[mt][nt], ah[mt], bh[nt]);
        }

        // store prefetched tile into the other buffer
        if (it < 31) {
            char* nb = smem + ((it + 1) & 1) * STGB;
            #pragma unroll
            for (int j = 0; j < 4; j++) {
                *(uint2*)(nb + soff[j])       = make_uint2(pa[j][0], pa[j][1]);
                *(uint2*)(nb + PLB + soff[j]) = make_uint2(pb[j][0], pb[j][1]);
            }
        }
        __syncthreads();
    }

    if (FUSE) {
        // recombine gate (cols 0..63) with up (cols 64..127) through smem
        float* s = (float*)smem;   // stride 132 floats, 128x128 tile (67.6 KB)
        #pragma unroll
        for (int mt = 0; mt < 2; mt++) {
            int r = wm + mt * 16 + gid;
            #pragma unroll
            for (int nt = 0; nt < 8; nt++) {
                int c = wn + nt * 8 + 2 * tig;
                *(float2*)&s[r * 132 + c]       = make_float2(acc[mt][nt][0], acc[mt][nt][1]);
                *(float2*)&s[(r + 8) * 132 + c] = make_float2(acc[mt][nt][2], acc[mt][nt][3]);
            }
        }
        __syncthreads();
        #pragma unroll
        for (int j = 0; j < 8; j++) {
            int u = tid + 256 * j;
            int r = u >> 4, cf = u & 15;
            int c = cf * 4;
            int p = row0 + r;
            if (p < rend) {
                float4 g = *(const float4*)&s[r * 132 + c];
                float4 up = *(const float4*)&s[r * 132 + 64 + c];
                float4 o;
                o.x = silu_f(g.x) * up.x; o.y = silu_f(g.y) * up.y;
                o.z = silu_f(g.z) * up.z; o.w = silu_f(g.w) * up.w;
                *(float4*)&D[(size_t)p * I_ + n0 + c] = o;
            }
        }
    } else {
        #pragma unroll
        for (int mt = 0; mt < 2; mt++) {
            int rr0 = row0 + wm + mt * 16 + gid;
            int rr1 = rr0 + 8;
            #pragma unroll
            for (int nt = 0; nt < 8; nt++) {
                int cc = n0 + wn + nt * 8 + 2 * tig;
                if (rr0 < rend)
                    *(float2*)&D[(size_t)rr0 * H_ + cc] = make_float2(acc[mt][nt][0], acc[mt][nt][1]);
                if (rr1 < rend)
                    *(float2*)&D[(size_t)rr1 * H_ + cc] = make_float2(acc[mt][nt][2], acc[mt][nt][3]);
            }
        }
    }
}

// ---------------- combine ----------------
__global__ void combine_kernel(const float* __restrict__ tw, float* __restrict__ out) {
    int t = blockIdx.x;
    __shared__ int   pos[K_];
    __shared__ float w[K_];
    if (threadIdx.x < K_) {
        pos[threadIdx.x] = g_pos[t * K_ + threadIdx.x];
        w[threadIdx.x]   = tw[t * K_ + threadIdx.x];
    }
    __syncthreads();
    int h = 4 * threadIdx.x;
    float4 acc = {0.f, 0.f, 0.f, 0.f};
    #pragma unroll
    for (int k = 0; k < K_; k++) {
        float4 v = *(const float4*)&g_down[(size_t)pos[k] * H_ + h];
        float wk = w[k];
        acc.x += wk * v.x; acc.y += wk * v.y;
        acc.z += wk * v.z; acc.w += wk * v.w;
    }
    *(float4*)&out[(size_t)t * H_ + h] = acc;
}

// ---------------- launch ----------------
extern "C" void kernel_launch(void* const* d_in, const int* in_sizes, int n_in,
                              void* d_out, int out_size) {
    const float* hidden = (const float*)d_in[0];
    const int*   tk_idx = (const int*)d_in[1];
    const float* tk_w   = (const float*)d_in[2];
    const float* gup    = (const float*)d_in[3];
    const float* dproj  = (const float*)d_in[4];
    float*       out    = (float*)d_out;

    float* act_p;  cudaGetSymbolAddress((void**)&act_p,  g_act);
    float* down_p; cudaGetSymbolAddress((void**)&down_p, g_down);

    cudaFuncSetAttribute(gemm_f16<1>, cudaFuncAttributeMaxDynamicSharedMemorySize, GSMEM_FUSE);
    cudaFuncSetAttribute(gemm_f16<0>, cudaFuncAttributeMaxDynamicSharedMemorySize, GSMEM);

    route_kernel<<<1, 1024>>>(tk_idx);
    gemm_f16<1><<<dim3(I_ / 64, TK_ / 128, E_), 256, GSMEM_FUSE>>>(hidden, gup, act_p);
    gemm_f16<0><<<dim3(H_ / 128, TK_ / 128, E_), 256, GSMEM>>>(act_p, dproj, down_p);
    combine_kernel<<<T_, 256>>>(tk_w, out);
}

// round 12
// speedup vs baseline: 3.4315x; 1.0060x over previous
#include <cuda_runtime.h>
#include <cuda_fp16.h>
#include <cstdint>
#include <math.h>

#define T_  1024
#define H_  1024
#define I_  1024
#define E_  16
#define K_  8
#define TK_ (T_ * K_)

// ---------------- scratch (no allocs allowed) ----------------
__device__ int    g_off[E_ + 1];
__device__ int    g_ptok[TK_];
__device__ int    g_pos[TK_];
__device__ __half q_xh[(size_t)T_ * H_];             // 2 MB
__device__ __half q_gh[(size_t)E_ * 2 * I_ * H_];    // 64 MB
__device__ __half q_dh[(size_t)E_ * H_ * I_];        // 32 MB
__device__ __half g_acth[(size_t)TK_ * I_];          // 16 MB
__device__ float  g_down[(size_t)TK_ * H_];          // 32 MB

// smem: 3-stage cp.async pipeline; per stage A+B fp16 planes, 80B pitch rows
#define PITCHB 80
#define PLB    (128 * PITCHB)    // 10240 B per plane
#define STGB   (2 * PLB)         // 20480 B per stage (A, B)
#define GSMEM  (3 * STGB)        // 61440 B

__device__ __forceinline__ uint32_t smem_u32(const void* p) {
    uint32_t a;
    asm("{ .reg .u64 t; cvta.to.shared.u64 t, %1; cvt.u32.u64 %0, t; }" : "=r"(a) : "l"(p));
    return a;
}
__device__ __forceinline__ float silu_f(float x) { return x / (1.0f + expf(-x)); }

__device__ __forceinline__ void mma_f16(float* c, const uint32_t* a, const uint32_t* b) {
    asm volatile(
        "mma.sync.aligned.m16n8k16.row.col.f32.f16.f16.f32 "
        "{%0,%1,%2,%3}, {%4,%5,%6,%7}, {%8,%9}, {%0,%1,%2,%3};"
        : "+f"(c[0]), "+f"(c[1]), "+f"(c[2]), "+f"(c[3])
        : "r"(a[0]), "r"(a[1]), "r"(a[2]), "r"(a[3]), "r"(b[0]), "r"(b[1]));
}
__device__ __forceinline__ void ldsm4(uint32_t* d, uint32_t addr) {
    asm volatile("ldmatrix.sync.aligned.m8n8.x4.shared.b16 {%0,%1,%2,%3}, [%4];"
        : "=r"(d[0]), "=r"(d[1]), "=r"(d[2]), "=r"(d[3]) : "r"(addr));
}
__device__ __forceinline__ void cp16(uint32_t dst, const void* src) {
    asm volatile("cp.async.cg.shared.global [%0], [%1], 16;" :: "r"(dst), "l"(src));
}
__device__ __forceinline__ uint32_t h2u(__half2 v) {
    return *reinterpret_cast<uint32_t*>(&v);
}

// ---------------- fp32 -> fp16 pre-pass (pure bandwidth) ----------------
__global__ void cvt_kernel(const float* __restrict__ src, __half* __restrict__ dst) {
    int i = blockIdx.x * 256 + threadIdx.x;
    float4 v = ((const float4*)src)[i];
    uint2 o = make_uint2(h2u(__floats2half2_rn(v.x, v.y)),
                         h2u(__floats2half2_rn(v.z, v.w)));
    ((uint2*)dst)[i] = o;
}

// ---------------- routing: stable chunked histogram ----------------
__global__ void route_kernel(const int* __restrict__ idx) {
    __shared__ int cnt[1024];
    __shared__ int off[1025];
    __shared__ int s_stride;
    int tid = threadIdx.x;
    if (tid == 0) {
        int nz = 0;
        #pragma unroll 1
        for (int j = 1; j < 256; j += 2) nz |= (idx[j] != 0);
        s_stride = nz ? 1 : 2;   // int32 vs int64 payload
    }
    __syncthreads();
    int stride = s_stride;
    int e = tid >> 6, c = tid & 63;
    int j0 = c * 128, j1 = j0 + 128;
    int cn = 0;
    for (int j = j0; j < j1; j++) cn += (idx[j * stride] == e);
    cnt[tid] = cn;
    __syncthreads();
    if (tid == 0) {
        int a = 0;
        for (int i = 0; i < 1024; i++) { off[i] = a; a += cnt[i]; }
        off[1024] = a;
        for (int ee = 0; ee <= E_; ee++) g_off[ee] = off[ee * 64];
    }
    __syncthreads();
    int p = off[tid];
    for (int j = j0; j < j1; j++) {
        if (idx[j * stride] == e) { g_ptok[p] = j >> 3; g_pos[j] = p; p++; }
    }
}

// ---------------------------------------------------------------------------
// Grouped GEMM, 1-pass fp16 mma.sync m16n8k16 on pre-converted fp16 operands.
// CTA tile 128(M)x128(N), BK=32, 256 threads, 8 warps (4m x 2n), warp 32x64.
// 3-stage cp.async pipeline (R6 pattern), ldmatrix.x4 fragments (R10 layout).
// FUSE=1: A gathered from q_xh, B rows = 64 gate + 64 up of i-block;
//         epilogue silu(gate)*up -> g_acth (fp16).
// FUSE=0: A = g_acth rows, B = q_dh; epilogue -> g_down (fp32).
// ---------------------------------------------------------------------------
template <int FUSE>
__global__ void __launch_bounds__(256, 2)
gemm_f16(const __half* __restrict__ A, const __half* __restrict__ B,
         __half* __restrict__ Dh, float* __restrict__ Df) {
    int e    = blockIdx.z;
    int rbeg = g_off[e], rend = g_off[e + 1];
    int row0 = rbeg + blockIdx.y * 128;
    if (row0 >= rend) return;
    int n0 = blockIdx.x * (FUSE ? 64 : 128);   // i-block (FUSE) or h-block

    extern __shared__ char smem[];
    uint32_t sb = smem_u32(smem);

    int tid  = threadIdx.x;
    int wid  = tid >> 5;
    int lane = tid & 31;
    int gid  = lane >> 2;
    int tig  = lane & 3;
    int wm   = (wid >> 1) * 32;   // 0,32,64,96
    int wn   = (wid & 1) * 64;    // 0,64

    // cp.async loader mapping: per plane 128 rows x 4 chunks(16B) = 512 chunks;
    // each thread owns 2 A-chunks + 2 B-chunks.
    const __half* asrc[2];
    const __half* bsrc[2];
    uint32_t sa[2], sbo[2];
    #pragma unroll
    for (int j = 0; j < 2; j++) {
        int u = tid + 256 * j;        // 0..511
        int r = u >> 2, c = u & 3;    // row, 16B-chunk
        int p = row0 + r; if (p >= rend) p = rend - 1;
        size_t arow = FUSE ? (size_t)g_ptok[p] : (size_t)p;
        asrc[j] = A + arow * 1024 + c * 8;
        int br;
        if (FUSE) br = (r < 64) ? (n0 + r) : (I_ + n0 + r - 64);
        else      br = n0 + r;
        bsrc[j] = B + ((size_t)e * (FUSE ? 2 * I_ : H_) + br) * 1024 + c * 8;
        sa[j]  = (uint32_t)(r * PITCHB + c * 16);
        sbo[j] = sa[j] + PLB;
    }

    auto issue = [&](int stg, int it) {
        uint32_t b = sb + stg * STGB;
        int ko = it * 32;   // halves per K-tile
        #pragma unroll
        for (int j = 0; j < 2; j++) cp16(b + sa[j],  asrc[j] + ko);
        #pragma unroll
        for (int j = 0; j < 2; j++) cp16(b + sbo[j], bsrc[j] + ko);
        asm volatile("cp.async.commit_group;" ::: "memory");
    };

    issue(0, 0);
    issue(1, 1);

    float acc[2][8][4];
    #pragma unroll
    for (int mt = 0; mt < 2; mt++)
        #pragma unroll
        for (int nt = 0; nt < 8; nt++)
            #pragma unroll
            for (int q = 0; q < 4; q++) acc[mt][nt][q] = 0.f;

    // ldmatrix lane offsets (R10/R11-verified)
    uint32_t aoff = (uint32_t)((((lane >> 3) & 1) * 8 + (lane & 7)) * PITCHB + (lane >> 4) * 16);
    uint32_t boff = (uint32_t)(((lane >> 4) * 8 + (lane & 7)) * PITCHB + ((lane >> 3) & 1) * 16);

    for (int it = 0; it < 32; it++) {
        if (it < 31) asm volatile("cp.async.wait_group 1;" ::: "memory");
        else         asm volatile("cp.async.wait_group 0;" ::: "memory");
        __syncthreads();
        uint32_t bb = sb + (it % 3) * STGB;

        #pragma unroll
        for (int ks = 0; ks < 2; ks++) {
            uint32_t kb = ks * 32;   // 16 halves = 32 B per k16 step
            uint32_t ah[2][4];
            #pragma unroll
            for (int mt = 0; mt < 2; mt++)
                ldsm4(ah[mt], bb + (wm + mt * 16) * PITCHB + kb + aoff);
            uint32_t bh[8][2];
            #pragma unroll
            for (int np = 0; np < 4; np++) {
                uint32_t r4[4];
                ldsm4(r4, bb + PLB + (wn + np * 16) * PITCHB + kb + boff);
                bh[2*np][0] = r4[0];   bh[2*np][1] = r4[1];
                bh[2*np+1][0] = r4[2]; bh[2*np+1][1] = r4[3];
            }
            #pragma unroll
            for (int nt = 0; nt < 8; nt++)
                #pragma unroll
                for (int mt = 0; mt < 2; mt++)
                    mma_f16(acc[mt][nt], ah[mt], bh[nt]);
        }

        if (it + 2 < 32) issue((it + 2) % 3, it + 2);
    }

    if (FUSE) {
        // odd-n warps hold "up" cols; stage them fp32, gate warps recombine.
        __syncthreads();
        float* s = (float*)smem;   // 128 x 68 fp32 = 34816 B
        if (wid & 1) {
            #pragma unroll
            for (int mt = 0; mt < 2; mt++) {
                int r = wm + mt * 16 + gid;
                #pragma unroll
                for (int nt = 0; nt < 8; nt++) {
                    int c = nt * 8 + 2 * tig;
                    *(float2*)&s[r * 68 + c]       = make_float2(acc[mt][nt][0], acc[mt][nt][1]);
                    *(float2*)&s[(r + 8) * 68 + c] = make_float2(acc[mt][nt][2], acc[mt][nt][3]);
                }
            }
        }
        __syncthreads();
        if (!(wid & 1)) {
            #pragma unroll
            for (int mt = 0; mt < 2; mt++) {
                int r = wm + mt * 16 + gid;
                int p0 = row0 + r, p1 = p0 + 8;
                #pragma unroll
                for (int nt = 0; nt < 8; nt++) {
                    int c = nt * 8 + 2 * tig;
                    if (p0 < rend) {
                        float2 u = *(float2*)&s[r * 68 + c];
                        __half2 o = __floats2half2_rn(silu_f(acc[mt][nt][0]) * u.x,
                                                      silu_f(acc[mt][nt][1]) * u.y);
                        *(__half2*)&Dh[(size_t)p0 * I_ + n0 + c] = o;
                    }
                    if (p1 < rend) {
                        float2 u = *(float2*)&s[(r + 8) * 68 + c];
                        __half2 o = __floats2half2_rn(silu_f(acc[mt][nt][2]) * u.x,
                                                      silu_f(acc[mt][nt][3]) * u.y);
                        *(__half2*)&Dh[(size_t)p1 * I_ + n0 + c] = o;
                    }
                }
            }
        }
    } else {
        #pragma unroll
        for (int mt = 0; mt < 2; mt++) {
            int rr0 = row0 + wm + mt * 16 + gid;
            int rr1 = rr0 + 8;
            #pragma unroll
            for (int nt = 0; nt < 8; nt++) {
                int cc = n0 + wn + nt * 8 + 2 * tig;
                if (rr0 < rend)
                    *(float2*)&Df[(size_t)rr0 * H_ + cc] = make_float2(acc[mt][nt][0], acc[mt][nt][1]);
                if (rr1 < rend)
                    *(float2*)&Df[(size_t)rr1 * H_ + cc] = make_float2(acc[mt][nt][2], acc[mt][nt][3]);
            }
        }
    }
}

// ---------------- combine ----------------
__global__ void combine_kernel(const float* __restrict__ tw, float* __restrict__ out) {
    int t = blockIdx.x;
    __shared__ int   pos[K_];
    __shared__ float w[K_];
    if (threadIdx.x < K_) {
        pos[threadIdx.x] = g_pos[t * K_ + threadIdx.x];
        w[threadIdx.x]   = tw[t * K_ + threadIdx.x];
    }
    __syncthreads();
    int h = 4 * threadIdx.x;
    float4 acc = {0.f, 0.f, 0.f, 0.f};
    #pragma unroll
    for (int k = 0; k < K_; k++) {
        float4 v = *(const float4*)&g_down[(size_t)pos[k] * H_ + h];
        float wk = w[k];
        acc.x += wk * v.x; acc.y += wk * v.y;
        acc.z += wk * v.z; acc.w += wk * v.w;
    }
    *(float4*)&out[(size_t)t * H_ + h] = acc;
}

// ---------------- launch ----------------
extern "C" void kernel_launch(void* const* d_in, const int* in_sizes, int n_in,
                              void* d_out, int out_size) {
    const float* hidden = (const float*)d_in[0];
    const int*   tk_idx = (const int*)d_in[1];
    const float* tk_w   = (const float*)d_in[2];
    const float* gup    = (const float*)d_in[3];
    const float* dproj  = (const float*)d_in[4];
    float*       out    = (float*)d_out;

    __half *xh, *gh, *dh, *acth;
    float  *down_p;
    cudaGetSymbolAddress((void**)&xh,   q_xh);
    cudaGetSymbolAddress((void**)&gh,   q_gh);
    cudaGetSymbolAddress((void**)&dh,   q_dh);
    cudaGetSymbolAddress((void**)&acth, g_acth);
    cudaGetSymbolAddress((void**)&down_p, g_down);

    cudaFuncSetAttribute(gemm_f16<1>, cudaFuncAttributeMaxDynamicSharedMemorySize, GSMEM);
    cudaFuncSetAttribute(gemm_f16<0>, cudaFuncAttributeMaxDynamicSharedMemorySize, GSMEM);

    route_kernel<<<1, 1024>>>(tk_idx);
    cvt_kernel<<<(T_ * H_) / 1024, 256>>>(hidden, xh);
    cvt_kernel<<<(E_ * 2 * I_ * H_) / 1024, 256>>>(gup, gh);
    cvt_kernel<<<(E_ * H_ * I_) / 1024, 256>>>(dproj, dh);

    gemm_f16<1><<<dim3(I_ / 64, TK_ / 128, E_), 256, GSMEM>>>(xh, gh, acth, nullptr);
    gemm_f16<0><<<dim3(H_ / 128, TK_ / 128, E_), 256, GSMEM>>>(acth, dh, nullptr, down_p);
    combine_kernel<<<T_, 256>>>(tk_w, out);
}

// round 13
// speedup vs baseline: 3.5223x; 1.0265x over previous
#include <cuda_runtime.h>
#include <cuda_fp16.h>
#include <cstdint>
#include <math.h>

#define T_  1024
#define H_  1024
#define I_  1024
#define E_  16
#define K_  8
#define TK_ (T_ * K_)

// ---------------- scratch (no allocs allowed) ----------------
__device__ int    g_off[E_ + 1];
__device__ int    g_ptok[TK_];
__device__ int    g_pos[TK_];
__device__ int    g_ntiles;
__device__ int    g_tile[96];                        // (e<<16)|row0 per m-tile
__device__ __half q_xh[(size_t)T_ * H_];             // 2 MB
__device__ __half q_gh[(size_t)E_ * 2 * I_ * H_];    // 64 MB
__device__ __half q_dh[(size_t)E_ * H_ * I_];        // 32 MB
__device__ __half g_acth[(size_t)TK_ * I_];          // 16 MB
__device__ float  g_down[(size_t)TK_ * H_];          // 32 MB

// smem: 3-stage cp.async pipeline; per stage A+B fp16 planes, BK=64, 144B pitch
#define PITCHB 144
#define PLB    (128 * PITCHB)    // 18432 B per plane
#define STGB   (2 * PLB)         // 36864 B per stage
#define GSMEM  (3 * STGB)        // 110592 B  (x2 CTAs = 221184 <= 228KB/SM)

#define NCTA   296               // persistent grid (2 per SM)

__device__ __forceinline__ uint32_t smem_u32(const void* p) {
    uint32_t a;
    asm("{ .reg .u64 t; cvta.to.shared.u64 t, %1; cvt.u32.u64 %0, t; }" : "=r"(a) : "l"(p));
    return a;
}
__device__ __forceinline__ float silu_f(float x) { return x / (1.0f + expf(-x)); }

__device__ __forceinline__ void mma_f16(float* c, const uint32_t* a, const uint32_t* b) {
    asm volatile(
        "mma.sync.aligned.m16n8k16.row.col.f32.f16.f16.f32 "
        "{%0,%1,%2,%3}, {%4,%5,%6,%7}, {%8,%9}, {%0,%1,%2,%3};"
        : "+f"(c[0]), "+f"(c[1]), "+f"(c[2]), "+f"(c[3])
        : "r"(a[0]), "r"(a[1]), "r"(a[2]), "r"(a[3]), "r"(b[0]), "r"(b[1]));
}
__device__ __forceinline__ void ldsm4(uint32_t* d, uint32_t addr) {
    asm volatile("ldmatrix.sync.aligned.m8n8.x4.shared.b16 {%0,%1,%2,%3}, [%4];"
        : "=r"(d[0]), "=r"(d[1]), "=r"(d[2]), "=r"(d[3]) : "r"(addr));
}
__device__ __forceinline__ void cp16(uint32_t dst, const void* src) {
    asm volatile("cp.async.cg.shared.global [%0], [%1], 16;" :: "r"(dst), "l"(src));
}
__device__ __forceinline__ uint32_t h2u(__half2 v) {
    return *reinterpret_cast<uint32_t*>(&v);
}

// ---------------- fp32 -> fp16 pre-pass (pure bandwidth) ----------------
__global__ void cvt_kernel(const float* __restrict__ src, __half* __restrict__ dst) {
    int i = blockIdx.x * 256 + threadIdx.x;
    float4 v = ((const float4*)src)[i];
    uint2 o = make_uint2(h2u(__floats2half2_rn(v.x, v.y)),
                         h2u(__floats2half2_rn(v.z, v.w)));
    ((uint2*)dst)[i] = o;
}

// ---------------- routing + tile-list build ----------------
__global__ void route_kernel(const int* __restrict__ idx) {
    __shared__ int cnt[1024];
    __shared__ int off[1025];
    __shared__ int s_stride;
    int tid = threadIdx.x;
    if (tid == 0) {
        int nz = 0;
        #pragma unroll 1
        for (int j = 1; j < 256; j += 2) nz |= (idx[j] != 0);
        s_stride = nz ? 1 : 2;   // int32 vs int64 payload
    }
    __syncthreads();
    int stride = s_stride;
    int e = tid >> 6, c = tid & 63;
    int j0 = c * 128, j1 = j0 + 128;
    int cn = 0;
    for (int j = j0; j < j1; j++) cn += (idx[j * stride] == e);
    cnt[tid] = cn;
    __syncthreads();
    if (tid == 0) {
        int a = 0;
        for (int i = 0; i < 1024; i++) { off[i] = a; a += cnt[i]; }
        off[1024] = a;
        int t = 0;
        for (int ee = 0; ee < E_; ee++) {
            int b = off[ee * 64], en = off[(ee + 1) * 64];
            g_off[ee] = b;
            for (int r0 = b; r0 < en; r0 += 128) g_tile[t++] = (ee << 16) | r0;
        }
        g_off[E_] = off[1024];
        g_ntiles = t;
    }
    __syncthreads();
    int p = off[tid];
    for (int j = j0; j < j1; j++) {
        if (idx[j * stride] == e) { g_ptok[p] = j >> 3; g_pos[j] = p; p++; }
    }
}

// ---------------------------------------------------------------------------
// Persistent grouped GEMM, 1-pass fp16 mma.sync m16n8k16, BK=64.
// 296 CTAs grid-stride over (m-tile x n-block) work items from g_tile[].
// CTA tile 128x128 (FUSE: 128x(64g+64u)), 256 thr, 8 warps (4m x 2n), warp 32x64.
// 3-stage cp.async pipeline, ldmatrix.x4 on 144B-pitch planes.
// FUSE=1: A gathered from q_xh, epilogue silu(gate)*up -> g_acth (fp16).
// FUSE=0: A = g_acth, B = q_dh, epilogue -> g_down (fp32).
// ---------------------------------------------------------------------------
template <int FUSE>
__global__ void __launch_bounds__(256, 2)
gemm_f16(const __half* __restrict__ A, const __half* __restrict__ B,
         __half* __restrict__ Dh, float* __restrict__ Df) {
    extern __shared__ char smem[];
    uint32_t sb = smem_u32(smem);

    int tid  = threadIdx.x;
    int wid  = tid >> 5;
    int lane = tid & 31;
    int gid  = lane >> 2;
    int tig  = lane & 3;
    int wm   = (wid >> 1) * 32;   // 0,32,64,96
    int wn   = (wid & 1) * 64;    // 0,64

    const int NX = FUSE ? 16 : 8;
    int ntile = g_ntiles;
    int nwork = ntile * NX;

    // ldmatrix lane offsets (layout family verified R10-R12)
    uint32_t aoff = (uint32_t)((((lane >> 3) & 1) * 8 + (lane & 7)) * PITCHB + (lane >> 4) * 16);
    uint32_t boff = (uint32_t)(((lane >> 4) * 8 + (lane & 7)) * PITCHB + ((lane >> 3) & 1) * 16);

    for (int w = blockIdx.x; w < nwork; w += gridDim.x) {
        int mt = w / NX, nx = w - mt * NX;
        int info = g_tile[mt];
        int e    = info >> 16;
        int row0 = info & 0xFFFF;
        int rend = g_off[e + 1];
        int n0   = nx * (FUSE ? 64 : 128);

        // cp.async loader mapping: per plane 128 rows x 8 chunks(16B);
        // each thread owns 4 A-chunks + 4 B-chunks.
        const __half* asrc[4];
        const __half* bsrc[4];
        uint32_t sa[4];
        #pragma unroll
        for (int j = 0; j < 4; j++) {
            int u = tid + 256 * j;        // 0..1023
            int r = u >> 3, c = u & 7;    // row, 16B-chunk
            int p = row0 + r; if (p >= rend) p = rend - 1;
            size_t arow = FUSE ? (size_t)g_ptok[p] : (size_t)p;
            asrc[j] = A + arow * 1024 + c * 8;
            int br;
            if (FUSE) br = (r < 64) ? (n0 + r) : (I_ + n0 + r - 64);
            else      br = n0 + r;
            bsrc[j] = B + ((size_t)e * (FUSE ? 2 * I_ : H_) + br) * 1024 + c * 8;
            sa[j] = (uint32_t)(r * PITCHB + c * 16);
        }

        auto issue = [&](int stg, int it) {
            uint32_t b = sb + stg * STGB;
            int ko = it * 64;   // halves per K-tile
            #pragma unroll
            for (int j = 0; j < 4; j++) cp16(b + sa[j], asrc[j] + ko);
            #pragma unroll
            for (int j = 0; j < 4; j++) cp16(b + PLB + sa[j], bsrc[j] + ko);
            asm volatile("cp.async.commit_group;" ::: "memory");
        };

        issue(0, 0);
        issue(1, 1);

        float acc[2][8][4];
        #pragma unroll
        for (int mt2 = 0; mt2 < 2; mt2++)
            #pragma unroll
            for (int nt = 0; nt < 8; nt++)
                #pragma unroll
                for (int q = 0; q < 4; q++) acc[mt2][nt][q] = 0.f;

        for (int it = 0; it < 16; it++) {
            if (it < 15) asm volatile("cp.async.wait_group 1;" ::: "memory");
            else         asm volatile("cp.async.wait_group 0;" ::: "memory");
            __syncthreads();
            uint32_t bb = sb + (it % 3) * STGB;

            #pragma unroll
            for (int ks = 0; ks < 4; ks++) {
                uint32_t kb = ks * 32;   // 16 halves = 32 B per k16 step
                uint32_t ah[2][4];
                #pragma unroll
                for (int m2 = 0; m2 < 2; m2++)
                    ldsm4(ah[m2], bb + (wm + m2 * 16) * PITCHB + kb + aoff);
                uint32_t bh[8][2];
                #pragma unroll
                for (int np = 0; np < 4; np++) {
                    uint32_t r4[4];
                    ldsm4(r4, bb + PLB + (wn + np * 16) * PITCHB + kb + boff);
                    bh[2*np][0] = r4[0];   bh[2*np][1] = r4[1];
                    bh[2*np+1][0] = r4[2]; bh[2*np+1][1] = r4[3];
                }
                #pragma unroll
                for (int nt = 0; nt < 8; nt++)
                    #pragma unroll
                    for (int m2 = 0; m2 < 2; m2++)
                        mma_f16(acc[m2][nt], ah[m2], bh[nt]);
            }

            if (it + 2 < 16) issue((it + 2) % 3, it + 2);
        }

        if (FUSE) {
            // odd-n warps hold "up" cols; stage fp32, even warps recombine.
            __syncthreads();
            float* s = (float*)smem;   // 128 x 68 fp32 = 34816 B (fits stage 0-1)
            if (wid & 1) {
                #pragma unroll
                for (int m2 = 0; m2 < 2; m2++) {
                    int r = wm + m2 * 16 + gid;
                    #pragma unroll
                    for (int nt = 0; nt < 8; nt++) {
                        int c = nt * 8 + 2 * tig;
                        *(float2*)&s[r * 68 + c]       = make_float2(acc[m2][nt][0], acc[m2][nt][1]);
                        *(float2*)&s[(r + 8) * 68 + c] = make_float2(acc[m2][nt][2], acc[m2][nt][3]);
                    }
                }
            }
            __syncthreads();
            if (!(wid & 1)) {
                #pragma unroll
                for (int m2 = 0; m2 < 2; m2++) {
                    int r = wm + m2 * 16 + gid;
                    int p0 = row0 + r, p1 = p0 + 8;
                    #pragma unroll
                    for (int nt = 0; nt < 8; nt++) {
                        int c = nt * 8 + 2 * tig;
                        if (p0 < rend) {
                            float2 u = *(float2*)&s[r * 68 + c];
                            __half2 o = __floats2half2_rn(silu_f(acc[m2][nt][0]) * u.x,
                                                          silu_f(acc[m2][nt][1]) * u.y);
                            *(__half2*)&Dh[(size_t)p0 * I_ + n0 + c] = o;
                        }
                        if (p1 < rend) {
                            float2 u = *(float2*)&s[(r + 8) * 68 + c];
                            __half2 o = __floats2half2_rn(silu_f(acc[m2][nt][2]) * u.x,
                                                          silu_f(acc[m2][nt][3]) * u.y);
                            *(__half2*)&Dh[(size_t)p1 * I_ + n0 + c] = o;
                        }
                    }
                }
            }
            __syncthreads();   // staging area reused by next tile's pipeline
        } else {
            #pragma unroll
            for (int m2 = 0; m2 < 2; m2++) {
                int rr0 = row0 + wm + m2 * 16 + gid;
                int rr1 = rr0 + 8;
                #pragma unroll
                for (int nt = 0; nt < 8; nt++) {
                    int cc = n0 + wn + nt * 8 + 2 * tig;
                    if (rr0 < rend)
                        *(float2*)&Df[(size_t)rr0 * H_ + cc] = make_float2(acc[m2][nt][0], acc[m2][nt][1]);
                    if (rr1 < rend)
                        *(float2*)&Df[(size_t)rr1 * H_ + cc] = make_float2(acc[m2][nt][2], acc[m2][nt][3]);
                }
            }
            __syncthreads();   // smem reused by next tile's pipeline
        }
    }
}

// ---------------- combine ----------------
__global__ void combine_kernel(const float* __restrict__ tw, float* __restrict__ out) {
    int t = blockIdx.x;
    __shared__ int   pos[K_];
    __shared__ float w[K_];
    if (threadIdx.x < K_) {
        pos[threadIdx.x] = g_pos[t * K_ + threadIdx.x];
        w[threadIdx.x]   = tw[t * K_ + threadIdx.x];
    }
    __syncthreads();
    int h = 4 * threadIdx.x;
    float4 acc = {0.f, 0.f, 0.f, 0.f};
    #pragma unroll
    for (int k = 0; k < K_; k++) {
        float4 v = *(const float4*)&g_down[(size_t)pos[k] * H_ + h];
        float wk = w[k];
        acc.x += wk * v.x; acc.y += wk * v.y;
        acc.z += wk * v.z; acc.w += wk * v.w;
    }
    *(float4*)&out[(size_t)t * H_ + h] = acc;
}

// ---------------- launch ----------------
extern "C" void kernel_launch(void* const* d_in, const int* in_sizes, int n_in,
                              void* d_out, int out_size) {
    const float* hidden = (const float*)d_in[0];
    const int*   tk_idx = (const int*)d_in[1];
    const float* tk_w   = (const float*)d_in[2];
    const float* gup    = (const float*)d_in[3];
    const float* dproj  = (const float*)d_in[4];
    float*       out    = (float*)d_out;

    __half *xh, *gh, *dh, *acth;
    float  *down_p;
    cudaGetSymbolAddress((void**)&xh,   q_xh);
    cudaGetSymbolAddress((void**)&gh,   q_gh);
    cudaGetSymbolAddress((void**)&dh,   q_dh);
    cudaGetSymbolAddress((void**)&acth, g_acth);
    cudaGetSymbolAddress((void**)&down_p, g_down);

    cudaFuncSetAttribute(gemm_f16<1>, cudaFuncAttributeMaxDynamicSharedMemorySize, GSMEM);
    cudaFuncSetAttribute(gemm_f16<0>, cudaFuncAttributeMaxDynamicSharedMemorySize, GSMEM);

    route_kernel<<<1, 1024>>>(tk_idx);
    cvt_kernel<<<(T_ * H_) / 1024, 256>>>(hidden, xh);
    cvt_kernel<<<(E_ * 2 * I_ * H_) / 1024, 256>>>(gup, gh);
    cvt_kernel<<<(E_ * H_ * I_) / 1024, 256>>>(dproj, dh);

    gemm_f16<1><<<NCTA, 256, GSMEM>>>(xh, gh, acth, nullptr);
    gemm_f16<0><<<NCTA, 256, GSMEM>>>(acth, dh, nullptr, down_p);
    combine_kernel<<<T_, 256>>>(tk_w, out);
}